// round 9
// baseline (speedup 1.0000x reference)
#include <cuda_runtime.h>
#include <cuda_bf16.h>
#include <math.h>
#include <stdint.h>

// Problem dims
#define BB   32
#define NN   256
#define DIMD 384
#define HH   6
#define DHD  64
#define MLPD 1536
#define DEPTH 12
#define INNERD 384
#define BN_ROWS (BB*NN)          // 8192
#define K3Q (3*DIMD)             // 1152
#define K3M (3*MLPD)             // 4608

// ---------------------------------------------------------------------------
// Device scratch
// ---------------------------------------------------------------------------
__device__ __align__(128) float g_x   [BN_ROWS*DIMD];
__device__ __align__(128) float g_qkv [BN_ROWS*K3Q];
__device__ __align__(128) float g_dots[(size_t)BB*HH*NN*NN];
__device__ __align__(128) float g_attn[(size_t)BB*HH*NN*NN];
__device__ __align__(128) __nv_bfloat16 g_yp[(size_t)BN_ROWS*K3Q];
__device__ __align__(128) __nv_bfloat16 g_op[(size_t)BN_ROWS*K3Q];
__device__ __align__(128) __nv_bfloat16 g_hp[(size_t)BN_ROWS*K3M];
__device__ __align__(128) __nv_bfloat16 g_wqkvp[(size_t)DEPTH*1152*K3Q];
__device__ __align__(128) __nv_bfloat16 g_wop  [(size_t)DEPTH*384 *K3Q];
__device__ __align__(128) __nv_bfloat16 g_w1p  [(size_t)DEPTH*1536*K3Q];
__device__ __align__(128) __nv_bfloat16 g_w2p  [(size_t)DEPTH*384 *K3M];

// ---------------------------------------------------------------------------
// Helpers
// ---------------------------------------------------------------------------
__device__ __forceinline__ uint32_t cvta_s(const void* p) {
    uint32_t a;
    asm("{ .reg .u64 t; cvta.to.shared.u64 t, %1; cvt.u32.u64 %0, t; }"
        : "=r"(a) : "l"(p));
    return a;
}
#define CP_ASYNC16(dst, src) \
    asm volatile("cp.async.cg.shared.global [%0], [%1], 16;" :: "r"(dst), "l"(src))
#define CP_COMMIT() asm volatile("cp.async.commit_group;")
#define CP_WAIT0()  asm volatile("cp.async.wait_group 0;" ::: "memory")

#define LDSM4(r0, r1, r2, r3, addr) \
    asm volatile("ldmatrix.sync.aligned.m8n8.x4.shared.b16 {%0,%1,%2,%3}, [%4];" \
                 : "=r"(r0), "=r"(r1), "=r"(r2), "=r"(r3) : "r"(addr))

__device__ __forceinline__ void mma16816(float* d, const uint32_t* a, const uint32_t* b) {
    asm volatile(
        "mma.sync.aligned.m16n8k16.row.col.f32.bf16.bf16.f32 "
        "{%0,%1,%2,%3}, {%4,%5,%6,%7}, {%8,%9}, {%0,%1,%2,%3};\n"
        : "+f"(d[0]), "+f"(d[1]), "+f"(d[2]), "+f"(d[3])
        : "r"(a[0]), "r"(a[1]), "r"(a[2]), "r"(a[3]), "r"(b[0]), "r"(b[1]));
}

__device__ __forceinline__ void bf_split(float v, __nv_bfloat16& hi, __nv_bfloat16& lo) {
    hi = __float2bfloat16(v);
    lo = __float2bfloat16(v - __bfloat162float(hi));
}

// ---------------------------------------------------------------------------
// Weight transpose + split: W[K,N] fp32 -> rows n of [hi(K)|hi(K)|lo(K)]
// ---------------------------------------------------------------------------
__global__ __launch_bounds__(256) void wconv_kernel(
    const float* __restrict__ W, __nv_bfloat16* __restrict__ out,
    int K, int N, int rowStride, int rowOff)
{
    __shared__ float tile[32][33];
    int k0 = blockIdx.y * 32, n0 = blockIdx.x * 32;
    int tx = threadIdx.x & 31, ty = threadIdx.x >> 5;
    #pragma unroll
    for (int i = 0; i < 4; i++) {
        int r = ty + i * 8;
        tile[r][tx] = W[(size_t)(k0 + r) * N + n0 + tx];
    }
    __syncthreads();
    #pragma unroll
    for (int i = 0; i < 4; i++) {
        int r = ty + i * 8;
        float w = tile[tx][r];
        __nv_bfloat16 hi, lo; bf_split(w, hi, lo);
        __nv_bfloat16* o = out + (size_t)(rowOff + n0 + r) * rowStride + k0 + tx;
        o[0]     = hi;
        o[K]     = hi;
        o[2 * K] = lo;
    }
}

// ---------------------------------------------------------------------------
// LayerNorm with split-bf16 output
// ---------------------------------------------------------------------------
__global__ __launch_bounds__(128) void ln_split_kernel(
    const float* __restrict__ x, const float* __restrict__ g,
    const float* __restrict__ b, __nv_bfloat16* __restrict__ yp)
{
    int row = blockIdx.x;
    int t = threadIdx.x;
    const float* xr = x + (size_t)row * DIMD;
    float v0 = xr[t], v1 = xr[t + 128], v2 = xr[t + 256];

    __shared__ float scratch[4];
    float s = v0 + v1 + v2;
    #pragma unroll
    for (int o = 16; o; o >>= 1) s += __shfl_xor_sync(0xffffffffu, s, o);
    if ((t & 31) == 0) scratch[t >> 5] = s;
    __syncthreads();
    s = scratch[0] + scratch[1] + scratch[2] + scratch[3];
    float mean = s * (1.0f / DIMD);

    float d0 = v0 - mean, d1 = v1 - mean, d2 = v2 - mean;
    float q = d0 * d0 + d1 * d1 + d2 * d2;
    __syncthreads();
    #pragma unroll
    for (int o = 16; o; o >>= 1) q += __shfl_xor_sync(0xffffffffu, q, o);
    if ((t & 31) == 0) scratch[t >> 5] = q;
    __syncthreads();
    q = scratch[0] + scratch[1] + scratch[2] + scratch[3];
    float rstd = rsqrtf(q * (1.0f / DIMD) + 1e-5f);

    __nv_bfloat16* yr = yp + (size_t)row * K3Q;
    #pragma unroll
    for (int seg = 0; seg < 3; seg++) {
        int c = t + seg * 128;
        float d = (seg == 0 ? d0 : seg == 1 ? d1 : d2);
        float v = d * rstd * g[c] + b[c];
        __nv_bfloat16 hi, lo; bf_split(v, hi, lo);
        yr[c]            = hi;
        yr[DIMD + c]     = lo;
        yr[2 * DIMD + c] = hi;
    }
}

// ---------------------------------------------------------------------------
// HMMA split-bf16 GEMM with ldmatrix mainloop.
// 128x128x32 tile, 8 warps (64x32 each), cp.async double buffer.
// EPI 0: fp32 out. EPI 1: gelu(c+bias) -> split bf16. EPI 2: (c+bias)*ls+res.
// ---------------------------------------------------------------------------
#define GPITCH 40   // halves per smem row (80B pitch; LDSM rows hit distinct banks)

template<int EPI>
__global__ __launch_bounds__(256) void tc_gemm(
    const __nv_bfloat16* __restrict__ A, const __nv_bfloat16* __restrict__ W,
    int K3, int N, int nchunks,
    float* __restrict__ Cf, __nv_bfloat16* __restrict__ Cs, int KsegOut,
    const float* __restrict__ bias, const float* __restrict__ ls,
    const float* __restrict__ res)
{
    __shared__ __nv_bfloat16 As[2][128 * GPITCH];
    __shared__ __nv_bfloat16 Bs[2][128 * GPITCH];

    int tid = threadIdx.x, lane = tid & 31, wid = tid >> 5;
    __builtin_assume(tid < 256);
    int wm = wid & 1, wn = wid >> 1;
    int m0 = blockIdx.y * 128, n0 = blockIdx.x * 128;

    // LDSM address geometry (in halves, relative to tile base)
    int a_row = (lane & 15);                 // row within m16 tile
    int a_col = (lane >> 4) * 8;             // k offset 0|8
    int b_row = (lane & 7) + ((lane >> 4) << 3);   // row within n16 tile
    int b_col = ((lane >> 3) & 1) * 8;       // k offset 0|8

    float acc[4][4][4] = {};

    auto load_chunk = [&](int c, int buf) {
        int k0 = c * 32;
        #pragma unroll
        for (int rep = 0; rep < 2; rep++) {
            int u = tid + rep * 256;
            int row = u >> 2, q = u & 3;
            uint32_t da = cvta_s(&As[buf][row * GPITCH + q * 8]);
            uint32_t db = cvta_s(&Bs[buf][row * GPITCH + q * 8]);
            CP_ASYNC16(da, A + (size_t)(m0 + row) * K3 + k0 + q * 8);
            CP_ASYNC16(db, W + (size_t)(n0 + row) * K3 + k0 + q * 8);
        }
        CP_COMMIT();
    };

    load_chunk(0, 0);
    for (int c = 0; c < nchunks; c++) {
        CP_WAIT0();
        __syncthreads();
        if (c + 1 < nchunks) load_chunk(c + 1, (c + 1) & 1);

        const __nv_bfloat16* Ab = As[c & 1];
        const __nv_bfloat16* Bb = Bs[c & 1];
        #pragma unroll
        for (int kk = 0; kk < 32; kk += 16) {
            uint32_t af[4][4], bf[4][2];
            #pragma unroll
            for (int mi = 0; mi < 4; mi++) {
                int r0 = wm * 64 + mi * 16;
                uint32_t ad = cvta_s(&Ab[(r0 + a_row) * GPITCH + kk + a_col]);
                LDSM4(af[mi][0], af[mi][1], af[mi][2], af[mi][3], ad);
            }
            #pragma unroll
            for (int nj = 0; nj < 2; nj++) {
                int nb = wn * 32 + nj * 16;
                uint32_t bd = cvta_s(&Bb[(nb + b_row) * GPITCH + kk + b_col]);
                uint32_t r0, r1, r2, r3;
                LDSM4(r0, r1, r2, r3, bd);
                bf[nj * 2][0] = r0; bf[nj * 2][1] = r1;
                bf[nj * 2 + 1][0] = r2; bf[nj * 2 + 1][1] = r3;
            }
            #pragma unroll
            for (int mi = 0; mi < 4; mi++)
                #pragma unroll
                for (int ni = 0; ni < 4; ni++)
                    mma16816(acc[mi][ni], af[mi], bf[ni]);
        }
    }

    #pragma unroll
    for (int mi = 0; mi < 4; mi++) {
        #pragma unroll
        for (int ni = 0; ni < 4; ni++) {
            int col = n0 + wn * 32 + ni * 8 + (lane & 3) * 2;
            #pragma unroll
            for (int hh = 0; hh < 2; hh++) {
                int m = m0 + wm * 64 + mi * 16 + (lane >> 2) + hh * 8;
                float v0 = acc[mi][ni][hh * 2 + 0];
                float v1 = acc[mi][ni][hh * 2 + 1];
                if (EPI == 0) {
                    Cf[(size_t)m * N + col]     = v0;
                    Cf[(size_t)m * N + col + 1] = v1;
                } else if (EPI == 1) {
                    #pragma unroll
                    for (int e = 0; e < 2; e++) {
                        float v = (e ? v1 : v0) + bias[col + e];
                        v = 0.5f * v * (1.0f + erff(v * 0.70710678118654752f));
                        __nv_bfloat16 hi, lo; bf_split(v, hi, lo);
                        __nv_bfloat16* o = Cs + (size_t)m * 3 * KsegOut + col + e;
                        o[0]           = hi;
                        o[KsegOut]     = lo;
                        o[2 * KsegOut] = hi;
                    }
                } else {
                    size_t i0 = (size_t)m * N + col;
                    Cf[i0]     = (v0 + bias[col])     * ls[col]     + res[i0];
                    Cf[i0 + 1] = (v1 + bias[col + 1]) * ls[col + 1] + res[i0 + 1];
                }
            }
        }
    }
}

// ---------------------------------------------------------------------------
// dots[b,h,i,j] = scale[h] * sum_d q[b,i,h,d]*k[b,j,h,d]  (fp32, fused qkv)
// ---------------------------------------------------------------------------
__global__ __launch_bounds__(256) void dots_kernel(
    const float* __restrict__ qkv, const float* __restrict__ scale,
    float* __restrict__ dots)
{
    int bh = blockIdx.z;
    int b = bh / HH, h = bh % HH;
    int i0 = blockIdx.y * 64, j0 = blockIdx.x * 64;
    __shared__ float Qs[64][65];
    __shared__ float Ks[64][65];
    int tid = threadIdx.x, tx = tid & 15, ty = tid >> 4;

    #pragma unroll
    for (int v = 0; v < 4; v++) {
        int lin = tid + v * 256;
        int r = lin >> 4, c = (lin & 15) * 4;
        float4 qa = *(const float4*)&qkv[(size_t)(b * NN + i0 + r) * K3Q + h * DHD + c];
        Qs[r][c] = qa.x; Qs[r][c + 1] = qa.y; Qs[r][c + 2] = qa.z; Qs[r][c + 3] = qa.w;
        float4 ka = *(const float4*)&qkv[(size_t)(b * NN + j0 + r) * K3Q + 384 + h * DHD + c];
        Ks[r][c] = ka.x; Ks[r][c + 1] = ka.y; Ks[r][c + 2] = ka.z; Ks[r][c + 3] = ka.w;
    }
    __syncthreads();

    float acc[4][4] = {};
    #pragma unroll 8
    for (int d = 0; d < 64; d++) {
        float a[4], bb[4];
        #pragma unroll
        for (int i = 0; i < 4; i++) a[i] = Qs[ty * 4 + i][d];
        #pragma unroll
        for (int j = 0; j < 4; j++) bb[j] = Ks[tx * 4 + j][d];
        #pragma unroll
        for (int i = 0; i < 4; i++)
            #pragma unroll
            for (int j = 0; j < 4; j++)
                acc[i][j] = fmaf(a[i], bb[j], acc[i][j]);
    }

    float sc = scale[h];
    #pragma unroll
    for (int i = 0; i < 4; i++)
        #pragma unroll
        for (int j = 0; j < 4; j++)
            dots[((size_t)bh * NN + i0 + ty * 4 + i) * NN + j0 + tx * 4 + j] = acc[i][j] * sc;
}

// ---------------------------------------------------------------------------
// Fused pre-mix -> mask -> softmax -> post-mix (fused 6-way reductions)
// ---------------------------------------------------------------------------
__global__ __launch_bounds__(256) void softmax_mix_kernel(
    const float* __restrict__ dots, const float* __restrict__ mp,
    const float* __restrict__ mq, float* __restrict__ attn)
{
    int b = blockIdx.x >> 8;
    int i = blockIdx.x & 255;
    int j = threadIdx.x;
    int lane = j & 31, wrp = j >> 5;

    __shared__ float smp[36], smq[36];
    __shared__ float red[8][6];
    if (j < 36) { smp[j] = mp[j]; smq[j] = mq[j]; }

    float raw[HH];
    #pragma unroll
    for (int h = 0; h < HH; h++)
        raw[h] = dots[(((size_t)(b * HH + h)) * NN + i) * NN + j];
    __syncthreads();

    float pm[HH];
    #pragma unroll
    for (int g = 0; g < HH; g++) {
        float s = 0.0f;
        #pragma unroll
        for (int h = 0; h < HH; h++) s = fmaf(raw[h], smp[h * HH + g], s);
        pm[g] = s;
    }
    if (j == i) {
        #pragma unroll
        for (int g = 0; g < HH; g++) pm[g] = -INFINITY;
    }

    float mx[HH];
    #pragma unroll
    for (int g = 0; g < HH; g++) mx[g] = pm[g];
    #pragma unroll
    for (int o = 16; o; o >>= 1)
        #pragma unroll
        for (int g = 0; g < HH; g++)
            mx[g] = fmaxf(mx[g], __shfl_xor_sync(0xffffffffu, mx[g], o));
    if (lane == 0)
        #pragma unroll
        for (int g = 0; g < HH; g++) red[wrp][g] = mx[g];
    __syncthreads();
    #pragma unroll
    for (int g = 0; g < HH; g++) {
        float m = red[0][g];
        #pragma unroll
        for (int w = 1; w < 8; w++) m = fmaxf(m, red[w][g]);
        mx[g] = m;
    }
    __syncthreads();

    float ex[HH], sm[HH];
    #pragma unroll
    for (int g = 0; g < HH; g++) { ex[g] = expf(pm[g] - mx[g]); sm[g] = ex[g]; }
    #pragma unroll
    for (int o = 16; o; o >>= 1)
        #pragma unroll
        for (int g = 0; g < HH; g++)
            sm[g] += __shfl_xor_sync(0xffffffffu, sm[g], o);
    if (lane == 0)
        #pragma unroll
        for (int g = 0; g < HH; g++) red[wrp][g] = sm[g];
    __syncthreads();
    float a[HH];
    #pragma unroll
    for (int g = 0; g < HH; g++) {
        float s = red[0][g];
        #pragma unroll
        for (int w = 1; w < 8; w++) s += red[w][g];
        a[g] = ex[g] / s;
    }

    #pragma unroll
    for (int g = 0; g < HH; g++) {
        float s = 0.0f;
        #pragma unroll
        for (int h = 0; h < HH; h++) s = fmaf(a[h], smq[h * HH + g], s);
        attn[(((size_t)(b * HH + g)) * NN + i) * NN + j] = s;
    }
}

// ---------------------------------------------------------------------------
// o'[b,i,:] split-bf16 = sum_j attn[b,h,i,j] * v[b,j,h,d]
// ---------------------------------------------------------------------------
__global__ __launch_bounds__(256) void attnv_kernel(
    const float* __restrict__ attn, const float* __restrict__ qkv,
    __nv_bfloat16* __restrict__ op)
{
    int bh = blockIdx.y;
    int b = bh / HH, h = bh % HH;
    int i0 = blockIdx.x * 64;
    __shared__ float As[32][68];
    __shared__ float Vs[32][64];
    int tid = threadIdx.x, tx = tid & 15, ty = tid >> 4;
    float acc[4][4] = {};

    const float* abase = attn + (size_t)bh * NN * NN;
    const float* vbase = qkv + 768 + h * DHD;

    for (int j0 = 0; j0 < NN; j0 += 32) {
        #pragma unroll
        for (int v = 0; v < 2; v++) {
            int lin = tid + v * 256;
            int r = lin >> 3, c = (lin & 7) * 4;
            float4 a = *(const float4*)&abase[(size_t)(i0 + r) * NN + j0 + c];
            As[c + 0][r] = a.x; As[c + 1][r] = a.y; As[c + 2][r] = a.z; As[c + 3][r] = a.w;
        }
        #pragma unroll
        for (int v = 0; v < 2; v++) {
            int lin = tid + v * 256;
            int r = lin >> 4, c = (lin & 15) * 4;
            *(float4*)&Vs[r][c] =
                *(const float4*)&vbase[(size_t)(b * NN + j0 + r) * K3Q + c];
        }
        __syncthreads();
        #pragma unroll
        for (int jj = 0; jj < 32; jj++) {
            float4 a4 = *(const float4*)&As[jj][ty * 4];
            float4 b4 = *(const float4*)&Vs[jj][tx * 4];
            float a[4] = {a4.x, a4.y, a4.z, a4.w};
            float bb[4] = {b4.x, b4.y, b4.z, b4.w};
            #pragma unroll
            for (int i = 0; i < 4; i++)
                #pragma unroll
                for (int j = 0; j < 4; j++)
                    acc[i][j] = fmaf(a[i], bb[j], acc[i][j]);
        }
        __syncthreads();
    }

    #pragma unroll
    for (int i = 0; i < 4; i++) {
        size_t row = (size_t)(b * NN + i0 + ty * 4 + i);
        #pragma unroll
        for (int j = 0; j < 4; j++) {
            int col = h * DHD + tx * 4 + j;
            __nv_bfloat16 hi, lo; bf_split(acc[i][j], hi, lo);
            __nv_bfloat16* o = op + row * K3Q + col;
            o[0]          = hi;
            o[INNERD]     = lo;
            o[2 * INNERD] = hi;
        }
    }
}

// ---------------------------------------------------------------------------
// Launch
// ---------------------------------------------------------------------------
extern "C" void kernel_launch(void* const* d_in, const int* in_sizes, int n_in,
                              void* d_out, int out_size)
{
    const float* x    = (const float*)d_in[0];
    const float* ln1g = (const float*)d_in[1];
    const float* ln1b = (const float*)d_in[2];
    const float* wq   = (const float*)d_in[3];
    const float* wkv  = (const float*)d_in[4];
    const float* scl  = (const float*)d_in[5];
    const float* mp   = (const float*)d_in[6];
    const float* mq   = (const float*)d_in[7];
    const float* wo   = (const float*)d_in[8];
    const float* bo   = (const float*)d_in[9];
    const float* ls1  = (const float*)d_in[10];
    const float* ln2g = (const float*)d_in[11];
    const float* ln2b = (const float*)d_in[12];
    const float* w1   = (const float*)d_in[13];
    const float* b1   = (const float*)d_in[14];
    const float* w2   = (const float*)d_in[15];
    const float* b2   = (const float*)d_in[16];
    const float* ls2  = (const float*)d_in[17];

    float *gx, *gqkv, *gdots, *gattn;
    __nv_bfloat16 *gyp, *gop, *ghp, *gwqkvp, *gwop, *gw1p, *gw2p;
    cudaGetSymbolAddress((void**)&gx,     g_x);
    cudaGetSymbolAddress((void**)&gqkv,   g_qkv);
    cudaGetSymbolAddress((void**)&gdots,  g_dots);
    cudaGetSymbolAddress((void**)&gattn,  g_attn);
    cudaGetSymbolAddress((void**)&gyp,    g_yp);
    cudaGetSymbolAddress((void**)&gop,    g_op);
    cudaGetSymbolAddress((void**)&ghp,    g_hp);
    cudaGetSymbolAddress((void**)&gwqkvp, g_wqkvp);
    cudaGetSymbolAddress((void**)&gwop,   g_wop);
    cudaGetSymbolAddress((void**)&gw1p,   g_w1p);
    cudaGetSymbolAddress((void**)&gw2p,   g_w2p);

    cudaMemcpyAsync(gx, x, (size_t)BN_ROWS * DIMD * sizeof(float),
                    cudaMemcpyDeviceToDevice, 0);

    // Weight conversion (transpose + bf16 split)
    for (int L = 0; L < DEPTH; L++) {
        wconv_kernel<<<dim3(384/32, 384/32), 256>>>(
            wq  + (size_t)L*DIMD*INNERD,   gwqkvp + (size_t)L*1152*K3Q, 384, 384,  K3Q, 0);
        wconv_kernel<<<dim3(768/32, 384/32), 256>>>(
            wkv + (size_t)L*DIMD*2*INNERD, gwqkvp + (size_t)L*1152*K3Q, 384, 768,  K3Q, 384);
        wconv_kernel<<<dim3(384/32, 384/32), 256>>>(
            wo  + (size_t)L*INNERD*DIMD,   gwop   + (size_t)L*384*K3Q,  384, 384,  K3Q, 0);
        wconv_kernel<<<dim3(1536/32, 384/32), 256>>>(
            w1  + (size_t)L*DIMD*MLPD,     gw1p   + (size_t)L*1536*K3Q, 384, 1536, K3Q, 0);
        wconv_kernel<<<dim3(384/32, 1536/32), 256>>>(
            w2  + (size_t)L*MLPD*DIMD,     gw2p   + (size_t)L*384*K3M,  1536, 384, K3M, 0);
    }

    for (int L = 0; L < DEPTH; L++) {
        const __nv_bfloat16* L_wqkvp = gwqkvp + (size_t)L*1152*K3Q;
        const __nv_bfloat16* L_wop   = gwop   + (size_t)L*384*K3Q;
        const __nv_bfloat16* L_w1p   = gw1p   + (size_t)L*1536*K3Q;
        const __nv_bfloat16* L_w2p   = gw2p   + (size_t)L*384*K3M;

        // Attention
        ln_split_kernel<<<BN_ROWS, 128>>>(gx, ln1g + L*DIMD, ln1b + L*DIMD, gyp);
        tc_gemm<0><<<dim3(1152/128, BN_ROWS/128), 256>>>(
            gyp, L_wqkvp, K3Q, 1152, K3Q/32, gqkv, nullptr, 0,
            nullptr, nullptr, nullptr);
        dots_kernel<<<dim3(NN/64, NN/64, BB*HH), 256>>>(gqkv, scl + L*HH, gdots);
        softmax_mix_kernel<<<BB*NN, 256>>>(gdots, mp + L*HH*HH, mq + L*HH*HH, gattn);
        attnv_kernel<<<dim3(NN/64, BB*HH), 256>>>(gattn, gqkv, gop);
        tc_gemm<2><<<dim3(384/128, BN_ROWS/128), 256>>>(
            gop, L_wop, K3Q, 384, K3Q/32, gx, nullptr, 0,
            bo + L*DIMD, ls1 + L*DIMD, gx);

        // FFN
        ln_split_kernel<<<BN_ROWS, 128>>>(gx, ln2g + L*DIMD, ln2b + L*DIMD, gyp);
        tc_gemm<1><<<dim3(1536/128, BN_ROWS/128), 256>>>(
            gyp, L_w1p, K3Q, 1536, K3Q/32, nullptr, ghp, MLPD,
            b1 + L*MLPD, nullptr, nullptr);
        tc_gemm<2><<<dim3(384/128, BN_ROWS/128), 256>>>(
            ghp, L_w2p, K3M, 384, K3M/32, gx, nullptr, 0,
            b2 + L*DIMD, ls2 + L*DIMD, gx);
    }

    cudaMemcpyAsync(d_out, gx, (size_t)BN_ROWS * DIMD * sizeof(float),
                    cudaMemcpyDeviceToDevice, 0);
}

// round 10
// speedup vs baseline: 1.5291x; 1.5291x over previous
#include <cuda_runtime.h>
#include <cuda_bf16.h>
#include <math.h>
#include <stdint.h>

// Problem dims
#define BB   32
#define NN   256
#define DIMD 384
#define HH   6
#define DHD  64
#define MLPD 1536
#define DEPTH 12
#define INNERD 384
#define BN_ROWS (BB*NN)          // 8192
#define K3Q (3*DIMD)             // 1152
#define K3M (3*MLPD)             // 4608

// ---------------------------------------------------------------------------
// Device scratch
// ---------------------------------------------------------------------------
__device__ __align__(128) float g_x   [BN_ROWS*DIMD];
__device__ __align__(128) float g_qkv [BN_ROWS*K3Q];
__device__ __align__(128) float g_dots[(size_t)BB*HH*NN*NN];
__device__ __align__(128) float g_attn[(size_t)BB*HH*NN*NN];
__device__ __align__(128) __nv_bfloat16 g_yp[(size_t)BN_ROWS*K3Q];
__device__ __align__(128) __nv_bfloat16 g_op[(size_t)BN_ROWS*K3Q];
__device__ __align__(128) __nv_bfloat16 g_hp[(size_t)BN_ROWS*K3M];
__device__ __align__(128) __nv_bfloat16 g_wqkvp[(size_t)DEPTH*1152*K3Q];
__device__ __align__(128) __nv_bfloat16 g_wop  [(size_t)DEPTH*384 *K3Q];
__device__ __align__(128) __nv_bfloat16 g_w1p  [(size_t)DEPTH*1536*K3Q];
__device__ __align__(128) __nv_bfloat16 g_w2p  [(size_t)DEPTH*384 *K3M];

// ---------------------------------------------------------------------------
// Helpers
// ---------------------------------------------------------------------------
__device__ __forceinline__ uint32_t cvta_s(const void* p) {
    uint32_t a;
    asm("{ .reg .u64 t; cvta.to.shared.u64 t, %1; cvt.u32.u64 %0, t; }"
        : "=r"(a) : "l"(p));
    return a;
}
#define CP_ASYNC16(dst, src) \
    asm volatile("cp.async.cg.shared.global [%0], [%1], 16;" :: "r"(dst), "l"(src))
#define CP_COMMIT()  asm volatile("cp.async.commit_group;")
#define CP_WAIT2()   asm volatile("cp.async.wait_group 2;" ::: "memory")

__device__ __forceinline__ void mma16816(float* d, const uint32_t* a, const uint32_t* b) {
    asm volatile(
        "mma.sync.aligned.m16n8k16.row.col.f32.bf16.bf16.f32 "
        "{%0,%1,%2,%3}, {%4,%5,%6,%7}, {%8,%9}, {%0,%1,%2,%3};\n"
        : "+f"(d[0]), "+f"(d[1]), "+f"(d[2]), "+f"(d[3])
        : "r"(a[0]), "r"(a[1]), "r"(a[2]), "r"(a[3]), "r"(b[0]), "r"(b[1]));
}

__device__ __forceinline__ void bf_split(float v, __nv_bfloat16& hi, __nv_bfloat16& lo) {
    hi = __float2bfloat16(v);
    lo = __float2bfloat16(v - __bfloat162float(hi));
}

// ---------------------------------------------------------------------------
// Weight transpose + split: W[K,N] fp32 -> rows n of [hi(K)|hi(K)|lo(K)]
// ---------------------------------------------------------------------------
__global__ __launch_bounds__(256) void wconv_kernel(
    const float* __restrict__ W, __nv_bfloat16* __restrict__ out,
    int K, int N, int rowStride, int rowOff)
{
    __shared__ float tile[32][33];
    int k0 = blockIdx.y * 32, n0 = blockIdx.x * 32;
    int tx = threadIdx.x & 31, ty = threadIdx.x >> 5;
    #pragma unroll
    for (int i = 0; i < 4; i++) {
        int r = ty + i * 8;
        tile[r][tx] = W[(size_t)(k0 + r) * N + n0 + tx];
    }
    __syncthreads();
    #pragma unroll
    for (int i = 0; i < 4; i++) {
        int r = ty + i * 8;
        float w = tile[tx][r];
        __nv_bfloat16 hi, lo; bf_split(w, hi, lo);
        __nv_bfloat16* o = out + (size_t)(rowOff + n0 + r) * rowStride + k0 + tx;
        o[0]     = hi;
        o[K]     = hi;
        o[2 * K] = lo;
    }
}

// ---------------------------------------------------------------------------
// LayerNorm with split-bf16 output
// ---------------------------------------------------------------------------
__global__ __launch_bounds__(128) void ln_split_kernel(
    const float* __restrict__ x, const float* __restrict__ g,
    const float* __restrict__ b, __nv_bfloat16* __restrict__ yp)
{
    int row = blockIdx.x;
    int t = threadIdx.x;
    const float* xr = x + (size_t)row * DIMD;
    float v0 = xr[t], v1 = xr[t + 128], v2 = xr[t + 256];

    __shared__ float scratch[4];
    float s = v0 + v1 + v2;
    #pragma unroll
    for (int o = 16; o; o >>= 1) s += __shfl_xor_sync(0xffffffffu, s, o);
    if ((t & 31) == 0) scratch[t >> 5] = s;
    __syncthreads();
    s = scratch[0] + scratch[1] + scratch[2] + scratch[3];
    float mean = s * (1.0f / DIMD);

    float d0 = v0 - mean, d1 = v1 - mean, d2 = v2 - mean;
    float q = d0 * d0 + d1 * d1 + d2 * d2;
    __syncthreads();
    #pragma unroll
    for (int o = 16; o; o >>= 1) q += __shfl_xor_sync(0xffffffffu, q, o);
    if ((t & 31) == 0) scratch[t >> 5] = q;
    __syncthreads();
    q = scratch[0] + scratch[1] + scratch[2] + scratch[3];
    float rstd = rsqrtf(q * (1.0f / DIMD) + 1e-5f);

    __nv_bfloat16* yr = yp + (size_t)row * K3Q;
    #pragma unroll
    for (int seg = 0; seg < 3; seg++) {
        int c = t + seg * 128;
        float d = (seg == 0 ? d0 : seg == 1 ? d1 : d2);
        float v = d * rstd * g[c] + b[c];
        __nv_bfloat16 hi, lo; bf_split(v, hi, lo);
        yr[c]            = hi;
        yr[DIMD + c]     = lo;
        yr[2 * DIMD + c] = hi;
    }
}

// ---------------------------------------------------------------------------
// HMMA split-bf16 GEMM, 4-stage cp.async pipeline (dynamic smem, 80KB).
// 128x128x32 tile, 8 warps (64x32 each), scalar-LDS fragment loads (proven).
// EPI 0: fp32 out. EPI 1: gelu(c+bias) -> split bf16. EPI 2: (c+bias)*ls+res.
// ---------------------------------------------------------------------------
#define GPITCH 40                         // halves per smem row
#define STAGE_H (128 * GPITCH)            // halves per stage per array
#define NSTAGE 4
#define GEMM_DSMEM (2 * NSTAGE * STAGE_H * 2)   // bytes = 81920

template<int EPI>
__global__ __launch_bounds__(256) void tc_gemm(
    const __nv_bfloat16* __restrict__ A, const __nv_bfloat16* __restrict__ W,
    int K3, int N, int nchunks,
    float* __restrict__ Cf, __nv_bfloat16* __restrict__ Cs, int KsegOut,
    const float* __restrict__ bias, const float* __restrict__ ls,
    const float* __restrict__ res)
{
    extern __shared__ __nv_bfloat16 dsm[];
    __nv_bfloat16* Asm = dsm;                       // NSTAGE stages
    __nv_bfloat16* Bsm = dsm + NSTAGE * STAGE_H;

    int tid = threadIdx.x, lane = tid & 31, wid = tid >> 5;
    __builtin_assume(tid < 256);
    int wm = wid & 1, wn = wid >> 1;
    int m0 = blockIdx.y * 128, n0 = blockIdx.x * 128;

    float acc[4][4][4] = {};

    auto load_chunk = [&](int c) {
        int buf = c & (NSTAGE - 1);
        int k0 = c * 32;
        #pragma unroll
        for (int rep = 0; rep < 2; rep++) {
            int u = tid + rep * 256;
            int row = u >> 2, q = u & 3;
            uint32_t da = cvta_s(&Asm[buf * STAGE_H + row * GPITCH + q * 8]);
            uint32_t db = cvta_s(&Bsm[buf * STAGE_H + row * GPITCH + q * 8]);
            CP_ASYNC16(da, A + (size_t)(m0 + row) * K3 + k0 + q * 8);
            CP_ASYNC16(db, W + (size_t)(n0 + row) * K3 + k0 + q * 8);
        }
        CP_COMMIT();
    };

    load_chunk(0);
    load_chunk(1);
    load_chunk(2);

    for (int c = 0; c < nchunks; c++) {
        CP_WAIT2();                 // with 1 group/iter committed: group c complete
        __syncthreads();
        if (c + 3 < nchunks) load_chunk(c + 3);
        else                 CP_COMMIT();          // keep group numbering

        const __nv_bfloat16* Ab = Asm + (c & (NSTAGE - 1)) * STAGE_H;
        const __nv_bfloat16* Bb = Bsm + (c & (NSTAGE - 1)) * STAGE_H;
        #pragma unroll
        for (int kk = 0; kk < 32; kk += 16) {
            int kc = kk + (lane & 3) * 2;
            uint32_t af[4][4], bf[4][2];
            #pragma unroll
            for (int mi = 0; mi < 4; mi++) {
                int r = wm * 64 + mi * 16 + (lane >> 2);
                af[mi][0] = *(const uint32_t*)&Ab[r * GPITCH + kc];
                af[mi][1] = *(const uint32_t*)&Ab[(r + 8) * GPITCH + kc];
                af[mi][2] = *(const uint32_t*)&Ab[r * GPITCH + kc + 8];
                af[mi][3] = *(const uint32_t*)&Ab[(r + 8) * GPITCH + kc + 8];
            }
            #pragma unroll
            for (int ni = 0; ni < 4; ni++) {
                int n = wn * 32 + ni * 8 + (lane >> 2);
                bf[ni][0] = *(const uint32_t*)&Bb[n * GPITCH + kc];
                bf[ni][1] = *(const uint32_t*)&Bb[n * GPITCH + kc + 8];
            }
            #pragma unroll
            for (int mi = 0; mi < 4; mi++)
                #pragma unroll
                for (int ni = 0; ni < 4; ni++)
                    mma16816(acc[mi][ni], af[mi], bf[ni]);
        }
    }

    #pragma unroll
    for (int mi = 0; mi < 4; mi++) {
        #pragma unroll
        for (int ni = 0; ni < 4; ni++) {
            int col = n0 + wn * 32 + ni * 8 + (lane & 3) * 2;
            #pragma unroll
            for (int hh = 0; hh < 2; hh++) {
                int m = m0 + wm * 64 + mi * 16 + (lane >> 2) + hh * 8;
                float v0 = acc[mi][ni][hh * 2 + 0];
                float v1 = acc[mi][ni][hh * 2 + 1];
                if (EPI == 0) {
                    Cf[(size_t)m * N + col]     = v0;
                    Cf[(size_t)m * N + col + 1] = v1;
                } else if (EPI == 1) {
                    #pragma unroll
                    for (int e = 0; e < 2; e++) {
                        float v = (e ? v1 : v0) + bias[col + e];
                        v = 0.5f * v * (1.0f + erff(v * 0.70710678118654752f));
                        __nv_bfloat16 hi, lo; bf_split(v, hi, lo);
                        __nv_bfloat16* o = Cs + (size_t)m * 3 * KsegOut + col + e;
                        o[0]           = hi;
                        o[KsegOut]     = lo;
                        o[2 * KsegOut] = hi;
                    }
                } else {
                    size_t i0 = (size_t)m * N + col;
                    Cf[i0]     = (v0 + bias[col])     * ls[col]     + res[i0];
                    Cf[i0 + 1] = (v1 + bias[col + 1]) * ls[col + 1] + res[i0 + 1];
                }
            }
        }
    }
}

// ---------------------------------------------------------------------------
// dots[b,h,i,j] = scale[h] * sum_d q[b,i,h,d]*k[b,j,h,d]  (fp32, fused qkv)
// ---------------------------------------------------------------------------
__global__ __launch_bounds__(256) void dots_kernel(
    const float* __restrict__ qkv, const float* __restrict__ scale,
    float* __restrict__ dots)
{
    int bh = blockIdx.z;
    int b = bh / HH, h = bh % HH;
    int i0 = blockIdx.y * 64, j0 = blockIdx.x * 64;
    __shared__ float Qs[64][65];
    __shared__ float Ks[64][65];
    int tid = threadIdx.x, tx = tid & 15, ty = tid >> 4;

    #pragma unroll
    for (int v = 0; v < 4; v++) {
        int lin = tid + v * 256;
        int r = lin >> 4, c = (lin & 15) * 4;
        float4 qa = *(const float4*)&qkv[(size_t)(b * NN + i0 + r) * K3Q + h * DHD + c];
        Qs[r][c] = qa.x; Qs[r][c + 1] = qa.y; Qs[r][c + 2] = qa.z; Qs[r][c + 3] = qa.w;
        float4 ka = *(const float4*)&qkv[(size_t)(b * NN + j0 + r) * K3Q + 384 + h * DHD + c];
        Ks[r][c] = ka.x; Ks[r][c + 1] = ka.y; Ks[r][c + 2] = ka.z; Ks[r][c + 3] = ka.w;
    }
    __syncthreads();

    float acc[4][4] = {};
    #pragma unroll 8
    for (int d = 0; d < 64; d++) {
        float a[4], bb[4];
        #pragma unroll
        for (int i = 0; i < 4; i++) a[i] = Qs[ty * 4 + i][d];
        #pragma unroll
        for (int j = 0; j < 4; j++) bb[j] = Ks[tx * 4 + j][d];
        #pragma unroll
        for (int i = 0; i < 4; i++)
            #pragma unroll
            for (int j = 0; j < 4; j++)
                acc[i][j] = fmaf(a[i], bb[j], acc[i][j]);
    }

    float sc = scale[h];
    #pragma unroll
    for (int i = 0; i < 4; i++)
        #pragma unroll
        for (int j = 0; j < 4; j++)
            dots[((size_t)bh * NN + i0 + ty * 4 + i) * NN + j0 + tx * 4 + j] = acc[i][j] * sc;
}

// ---------------------------------------------------------------------------
// Fused pre-mix -> mask -> softmax -> post-mix (6-way interleaved reductions)
// ---------------------------------------------------------------------------
__global__ __launch_bounds__(256) void softmax_mix_kernel(
    const float* __restrict__ dots, const float* __restrict__ mp,
    const float* __restrict__ mq, float* __restrict__ attn)
{
    int b = blockIdx.x >> 8;
    int i = blockIdx.x & 255;
    int j = threadIdx.x;
    int lane = j & 31, wrp = j >> 5;

    __shared__ float smp[36], smq[36];
    __shared__ float red[8][6];
    if (j < 36) { smp[j] = mp[j]; smq[j] = mq[j]; }

    float raw[HH];
    #pragma unroll
    for (int h = 0; h < HH; h++)
        raw[h] = dots[(((size_t)(b * HH + h)) * NN + i) * NN + j];
    __syncthreads();

    float pm[HH];
    #pragma unroll
    for (int g = 0; g < HH; g++) {
        float s = 0.0f;
        #pragma unroll
        for (int h = 0; h < HH; h++) s = fmaf(raw[h], smp[h * HH + g], s);
        pm[g] = s;
    }
    if (j == i) {
        #pragma unroll
        for (int g = 0; g < HH; g++) pm[g] = -INFINITY;
    }

    float mx[HH];
    #pragma unroll
    for (int g = 0; g < HH; g++) mx[g] = pm[g];
    #pragma unroll
    for (int o = 16; o; o >>= 1)
        #pragma unroll
        for (int g = 0; g < HH; g++)
            mx[g] = fmaxf(mx[g], __shfl_xor_sync(0xffffffffu, mx[g], o));
    if (lane == 0)
        #pragma unroll
        for (int g = 0; g < HH; g++) red[wrp][g] = mx[g];
    __syncthreads();
    #pragma unroll
    for (int g = 0; g < HH; g++) {
        float m = red[0][g];
        #pragma unroll
        for (int w = 1; w < 8; w++) m = fmaxf(m, red[w][g]);
        mx[g] = m;
    }
    __syncthreads();

    float ex[HH], sm[HH];
    #pragma unroll
    for (int g = 0; g < HH; g++) { ex[g] = expf(pm[g] - mx[g]); sm[g] = ex[g]; }
    #pragma unroll
    for (int o = 16; o; o >>= 1)
        #pragma unroll
        for (int g = 0; g < HH; g++)
            sm[g] += __shfl_xor_sync(0xffffffffu, sm[g], o);
    if (lane == 0)
        #pragma unroll
        for (int g = 0; g < HH; g++) red[wrp][g] = sm[g];
    __syncthreads();
    float a[HH];
    #pragma unroll
    for (int g = 0; g < HH; g++) {
        float s = red[0][g];
        #pragma unroll
        for (int w = 1; w < 8; w++) s += red[w][g];
        a[g] = ex[g] / s;
    }

    #pragma unroll
    for (int g = 0; g < HH; g++) {
        float s = 0.0f;
        #pragma unroll
        for (int h = 0; h < HH; h++) s = fmaf(a[h], smq[h * HH + g], s);
        attn[(((size_t)(b * HH + g)) * NN + i) * NN + j] = s;
    }
}

// ---------------------------------------------------------------------------
// o'[b,i,:] split-bf16 = sum_j attn[b,h,i,j] * v[b,j,h,d]
// ---------------------------------------------------------------------------
__global__ __launch_bounds__(256) void attnv_kernel(
    const float* __restrict__ attn, const float* __restrict__ qkv,
    __nv_bfloat16* __restrict__ op)
{
    int bh = blockIdx.y;
    int b = bh / HH, h = bh % HH;
    int i0 = blockIdx.x * 64;
    __shared__ float As[32][68];
    __shared__ float Vs[32][64];
    int tid = threadIdx.x, tx = tid & 15, ty = tid >> 4;
    float acc[4][4] = {};

    const float* abase = attn + (size_t)bh * NN * NN;
    const float* vbase = qkv + 768 + h * DHD;

    for (int j0 = 0; j0 < NN; j0 += 32) {
        #pragma unroll
        for (int v = 0; v < 2; v++) {
            int lin = tid + v * 256;
            int r = lin >> 3, c = (lin & 7) * 4;
            float4 a = *(const float4*)&abase[(size_t)(i0 + r) * NN + j0 + c];
            As[c + 0][r] = a.x; As[c + 1][r] = a.y; As[c + 2][r] = a.z; As[c + 3][r] = a.w;
        }
        #pragma unroll
        for (int v = 0; v < 2; v++) {
            int lin = tid + v * 256;
            int r = lin >> 4, c = (lin & 15) * 4;
            *(float4*)&Vs[r][c] =
                *(const float4*)&vbase[(size_t)(b * NN + j0 + r) * K3Q + c];
        }
        __syncthreads();
        #pragma unroll
        for (int jj = 0; jj < 32; jj++) {
            float4 a4 = *(const float4*)&As[jj][ty * 4];
            float4 b4 = *(const float4*)&Vs[jj][tx * 4];
            float a[4] = {a4.x, a4.y, a4.z, a4.w};
            float bb[4] = {b4.x, b4.y, b4.z, b4.w};
            #pragma unroll
            for (int i = 0; i < 4; i++)
                #pragma unroll
                for (int j = 0; j < 4; j++)
                    acc[i][j] = fmaf(a[i], bb[j], acc[i][j]);
        }
        __syncthreads();
    }

    #pragma unroll
    for (int i = 0; i < 4; i++) {
        size_t row = (size_t)(b * NN + i0 + ty * 4 + i);
        #pragma unroll
        for (int j = 0; j < 4; j++) {
            int col = h * DHD + tx * 4 + j;
            __nv_bfloat16 hi, lo; bf_split(acc[i][j], hi, lo);
            __nv_bfloat16* o = op + row * K3Q + col;
            o[0]          = hi;
            o[INNERD]     = lo;
            o[2 * INNERD] = hi;
        }
    }
}

// ---------------------------------------------------------------------------
// Launch
// ---------------------------------------------------------------------------
extern "C" void kernel_launch(void* const* d_in, const int* in_sizes, int n_in,
                              void* d_out, int out_size)
{
    const float* x    = (const float*)d_in[0];
    const float* ln1g = (const float*)d_in[1];
    const float* ln1b = (const float*)d_in[2];
    const float* wq   = (const float*)d_in[3];
    const float* wkv  = (const float*)d_in[4];
    const float* scl  = (const float*)d_in[5];
    const float* mp   = (const float*)d_in[6];
    const float* mq   = (const float*)d_in[7];
    const float* wo   = (const float*)d_in[8];
    const float* bo   = (const float*)d_in[9];
    const float* ls1  = (const float*)d_in[10];
    const float* ln2g = (const float*)d_in[11];
    const float* ln2b = (const float*)d_in[12];
    const float* w1   = (const float*)d_in[13];
    const float* b1   = (const float*)d_in[14];
    const float* w2   = (const float*)d_in[15];
    const float* b2   = (const float*)d_in[16];
    const float* ls2  = (const float*)d_in[17];

    // Raise dynamic smem limit for the GEMM kernels (idempotent; not a stream op)
    cudaFuncSetAttribute(tc_gemm<0>, cudaFuncAttributeMaxDynamicSharedMemorySize, GEMM_DSMEM);
    cudaFuncSetAttribute(tc_gemm<1>, cudaFuncAttributeMaxDynamicSharedMemorySize, GEMM_DSMEM);
    cudaFuncSetAttribute(tc_gemm<2>, cudaFuncAttributeMaxDynamicSharedMemorySize, GEMM_DSMEM);

    float *gx, *gqkv, *gdots, *gattn;
    __nv_bfloat16 *gyp, *gop, *ghp, *gwqkvp, *gwop, *gw1p, *gw2p;
    cudaGetSymbolAddress((void**)&gx,     g_x);
    cudaGetSymbolAddress((void**)&gqkv,   g_qkv);
    cudaGetSymbolAddress((void**)&gdots,  g_dots);
    cudaGetSymbolAddress((void**)&gattn,  g_attn);
    cudaGetSymbolAddress((void**)&gyp,    g_yp);
    cudaGetSymbolAddress((void**)&gop,    g_op);
    cudaGetSymbolAddress((void**)&ghp,    g_hp);
    cudaGetSymbolAddress((void**)&gwqkvp, g_wqkvp);
    cudaGetSymbolAddress((void**)&gwop,   g_wop);
    cudaGetSymbolAddress((void**)&gw1p,   g_w1p);
    cudaGetSymbolAddress((void**)&gw2p,   g_w2p);

    cudaMemcpyAsync(gx, x, (size_t)BN_ROWS * DIMD * sizeof(float),
                    cudaMemcpyDeviceToDevice, 0);

    // Weight conversion (transpose + bf16 split)
    for (int L = 0; L < DEPTH; L++) {
        wconv_kernel<<<dim3(384/32, 384/32), 256>>>(
            wq  + (size_t)L*DIMD*INNERD,   gwqkvp + (size_t)L*1152*K3Q, 384, 384,  K3Q, 0);
        wconv_kernel<<<dim3(768/32, 384/32), 256>>>(
            wkv + (size_t)L*DIMD*2*INNERD, gwqkvp + (size_t)L*1152*K3Q, 384, 768,  K3Q, 384);
        wconv_kernel<<<dim3(384/32, 384/32), 256>>>(
            wo  + (size_t)L*INNERD*DIMD,   gwop   + (size_t)L*384*K3Q,  384, 384,  K3Q, 0);
        wconv_kernel<<<dim3(1536/32, 384/32), 256>>>(
            w1  + (size_t)L*DIMD*MLPD,     gw1p   + (size_t)L*1536*K3Q, 384, 1536, K3Q, 0);
        wconv_kernel<<<dim3(384/32, 1536/32), 256>>>(
            w2  + (size_t)L*MLPD*DIMD,     gw2p   + (size_t)L*384*K3M,  1536, 384, K3M, 0);
    }

    for (int L = 0; L < DEPTH; L++) {
        const __nv_bfloat16* L_wqkvp = gwqkvp + (size_t)L*1152*K3Q;
        const __nv_bfloat16* L_wop   = gwop   + (size_t)L*384*K3Q;
        const __nv_bfloat16* L_w1p   = gw1p   + (size_t)L*1536*K3Q;
        const __nv_bfloat16* L_w2p   = gw2p   + (size_t)L*384*K3M;

        // Attention
        ln_split_kernel<<<BN_ROWS, 128>>>(gx, ln1g + L*DIMD, ln1b + L*DIMD, gyp);
        tc_gemm<0><<<dim3(1152/128, BN_ROWS/128), 256, GEMM_DSMEM>>>(
            gyp, L_wqkvp, K3Q, 1152, K3Q/32, gqkv, nullptr, 0,
            nullptr, nullptr, nullptr);
        dots_kernel<<<dim3(NN/64, NN/64, BB*HH), 256>>>(gqkv, scl + L*HH, gdots);
        softmax_mix_kernel<<<BB*NN, 256>>>(gdots, mp + L*HH*HH, mq + L*HH*HH, gattn);
        attnv_kernel<<<dim3(NN/64, BB*HH), 256>>>(gattn, gqkv, gop);
        tc_gemm<2><<<dim3(384/128, BN_ROWS/128), 256, GEMM_DSMEM>>>(
            gop, L_wop, K3Q, 384, K3Q/32, gx, nullptr, 0,
            bo + L*DIMD, ls1 + L*DIMD, gx);

        // FFN
        ln_split_kernel<<<BN_ROWS, 128>>>(gx, ln2g + L*DIMD, ln2b + L*DIMD, gyp);
        tc_gemm<1><<<dim3(1536/128, BN_ROWS/128), 256, GEMM_DSMEM>>>(
            gyp, L_w1p, K3Q, 1536, K3Q/32, nullptr, ghp, MLPD,
            b1 + L*MLPD, nullptr, nullptr);
        tc_gemm<2><<<dim3(384/128, BN_ROWS/128), 256, GEMM_DSMEM>>>(
            ghp, L_w2p, K3M, 384, K3M/32, gx, nullptr, 0,
            b2 + L*DIMD, ls2 + L*DIMD, gx);
    }

    cudaMemcpyAsync(d_out, gx, (size_t)BN_ROWS * DIMD * sizeof(float),
                    cudaMemcpyDeviceToDevice, 0);
}

// round 11
// speedup vs baseline: 2.7742x; 1.8143x over previous
#include <cuda_runtime.h>
#include <cuda_bf16.h>
#include <math.h>
#include <stdint.h>

// Problem dims
#define BB   32
#define NN   256
#define DIMD 384
#define HH   6
#define DHD  64
#define MLPD 1536
#define DEPTH 12
#define INNERD 384
#define BN_ROWS (BB*NN)          // 8192
#define K3Q (3*DIMD)             // 1152 (qkv output cols)

// ---------------------------------------------------------------------------
// Device scratch
// ---------------------------------------------------------------------------
__device__ __align__(128) float g_x   [BN_ROWS*DIMD];
__device__ __align__(128) float g_qkv [BN_ROWS*K3Q];
__device__ __align__(128) float g_dots[(size_t)BB*HH*NN*NN];
__device__ __align__(128) float g_attn[(size_t)BB*HH*NN*NN];
__device__ __align__(128) __nv_bfloat16 g_yp[(size_t)BN_ROWS*DIMD];
__device__ __align__(128) __nv_bfloat16 g_op[(size_t)BN_ROWS*DIMD];
__device__ __align__(128) __nv_bfloat16 g_hp[(size_t)BN_ROWS*MLPD];
__device__ __align__(128) __nv_bfloat16 g_wqkvp[(size_t)DEPTH*1152*DIMD];
__device__ __align__(128) __nv_bfloat16 g_wop  [(size_t)DEPTH*384 *DIMD];
__device__ __align__(128) __nv_bfloat16 g_w1p  [(size_t)DEPTH*1536*DIMD];
__device__ __align__(128) __nv_bfloat16 g_w2p  [(size_t)DEPTH*384 *MLPD];

// ---------------------------------------------------------------------------
// Helpers
// ---------------------------------------------------------------------------
__device__ __forceinline__ uint32_t cvta_s(const void* p) {
    uint32_t a;
    asm("{ .reg .u64 t; cvta.to.shared.u64 t, %1; cvt.u32.u64 %0, t; }"
        : "=r"(a) : "l"(p));
    return a;
}
#define CP_ASYNC16(dst, src) \
    asm volatile("cp.async.cg.shared.global [%0], [%1], 16;" :: "r"(dst), "l"(src))
#define CP_COMMIT()  asm volatile("cp.async.commit_group;")
#define CP_WAIT2()   asm volatile("cp.async.wait_group 2;" ::: "memory")

__device__ __forceinline__ void mma16816(float* d, const uint32_t* a, const uint32_t* b) {
    asm volatile(
        "mma.sync.aligned.m16n8k16.row.col.f32.bf16.bf16.f32 "
        "{%0,%1,%2,%3}, {%4,%5,%6,%7}, {%8,%9}, {%0,%1,%2,%3};\n"
        : "+f"(d[0]), "+f"(d[1]), "+f"(d[2]), "+f"(d[3])
        : "r"(a[0]), "r"(a[1]), "r"(a[2]), "r"(a[3]), "r"(b[0]), "r"(b[1]));
}

// ---------------------------------------------------------------------------
// Weight transpose to bf16: W[K,N] fp32 -> out[n][k] bf16 (row stride = K)
// ---------------------------------------------------------------------------
__global__ __launch_bounds__(256) void wconv_kernel(
    const float* __restrict__ W, __nv_bfloat16* __restrict__ out,
    int K, int N, int rowOff)
{
    __shared__ float tile[32][33];
    int k0 = blockIdx.y * 32, n0 = blockIdx.x * 32;
    int tx = threadIdx.x & 31, ty = threadIdx.x >> 5;
    #pragma unroll
    for (int i = 0; i < 4; i++) {
        int r = ty + i * 8;
        tile[r][tx] = W[(size_t)(k0 + r) * N + n0 + tx];
    }
    __syncthreads();
    #pragma unroll
    for (int i = 0; i < 4; i++) {
        int r = ty + i * 8;
        out[(size_t)(rowOff + n0 + r) * K + k0 + tx] = __float2bfloat16(tile[tx][r]);
    }
}

// ---------------------------------------------------------------------------
// LayerNorm -> plain bf16 output
// ---------------------------------------------------------------------------
__global__ __launch_bounds__(128) void ln_bf16_kernel(
    const float* __restrict__ x, const float* __restrict__ g,
    const float* __restrict__ b, __nv_bfloat16* __restrict__ yp)
{
    int row = blockIdx.x;
    int t = threadIdx.x;
    const float* xr = x + (size_t)row * DIMD;
    float v0 = xr[t], v1 = xr[t + 128], v2 = xr[t + 256];

    __shared__ float scratch[4];
    float s = v0 + v1 + v2;
    #pragma unroll
    for (int o = 16; o; o >>= 1) s += __shfl_xor_sync(0xffffffffu, s, o);
    if ((t & 31) == 0) scratch[t >> 5] = s;
    __syncthreads();
    s = scratch[0] + scratch[1] + scratch[2] + scratch[3];
    float mean = s * (1.0f / DIMD);

    float d0 = v0 - mean, d1 = v1 - mean, d2 = v2 - mean;
    float q = d0 * d0 + d1 * d1 + d2 * d2;
    __syncthreads();
    #pragma unroll
    for (int o = 16; o; o >>= 1) q += __shfl_xor_sync(0xffffffffu, q, o);
    if ((t & 31) == 0) scratch[t >> 5] = q;
    __syncthreads();
    q = scratch[0] + scratch[1] + scratch[2] + scratch[3];
    float rstd = rsqrtf(q * (1.0f / DIMD) + 1e-5f);

    __nv_bfloat16* yr = yp + (size_t)row * DIMD;
    yr[t]       = __float2bfloat16(d0 * rstd * g[t]       + b[t]);
    yr[t + 128] = __float2bfloat16(d1 * rstd * g[t + 128] + b[t + 128]);
    yr[t + 256] = __float2bfloat16(d2 * rstd * g[t + 256] + b[t + 256]);
}

// ---------------------------------------------------------------------------
// HMMA bf16 GEMM, 4-stage cp.async pipeline (dynamic smem, 80KB).
// 128x128x32 tile, 8 warps (64x32 each), scalar-LDS fragment loads.
// EPI 0: fp32 out. EPI 1: gelu(c+bias) -> bf16 (row stride KsegOut).
// EPI 2: (c+bias)*ls + res -> fp32.
// ---------------------------------------------------------------------------
#define GPITCH 40
#define STAGE_H (128 * GPITCH)
#define NSTAGE 4
#define GEMM_DSMEM (2 * NSTAGE * STAGE_H * 2)   // 81920 B

template<int EPI>
__global__ __launch_bounds__(256) void tc_gemm(
    const __nv_bfloat16* __restrict__ A, const __nv_bfloat16* __restrict__ W,
    int K3, int N, int nchunks,
    float* __restrict__ Cf, __nv_bfloat16* __restrict__ Cs, int KsegOut,
    const float* __restrict__ bias, const float* __restrict__ ls,
    const float* __restrict__ res)
{
    extern __shared__ __nv_bfloat16 dsm[];
    __nv_bfloat16* Asm = dsm;
    __nv_bfloat16* Bsm = dsm + NSTAGE * STAGE_H;

    int tid = threadIdx.x, lane = tid & 31, wid = tid >> 5;
    __builtin_assume(tid < 256);
    int wm = wid & 1, wn = wid >> 1;
    int m0 = blockIdx.y * 128, n0 = blockIdx.x * 128;

    float acc[4][4][4] = {};

    auto load_chunk = [&](int c) {
        int buf = c & (NSTAGE - 1);
        int k0 = c * 32;
        #pragma unroll
        for (int rep = 0; rep < 2; rep++) {
            int u = tid + rep * 256;
            int row = u >> 2, q = u & 3;
            uint32_t da = cvta_s(&Asm[buf * STAGE_H + row * GPITCH + q * 8]);
            uint32_t db = cvta_s(&Bsm[buf * STAGE_H + row * GPITCH + q * 8]);
            CP_ASYNC16(da, A + (size_t)(m0 + row) * K3 + k0 + q * 8);
            CP_ASYNC16(db, W + (size_t)(n0 + row) * K3 + k0 + q * 8);
        }
        CP_COMMIT();
    };

    load_chunk(0);
    load_chunk(1);
    load_chunk(2);

    for (int c = 0; c < nchunks; c++) {
        CP_WAIT2();
        __syncthreads();
        if (c + 3 < nchunks) load_chunk(c + 3);
        else                 CP_COMMIT();

        const __nv_bfloat16* Ab = Asm + (c & (NSTAGE - 1)) * STAGE_H;
        const __nv_bfloat16* Bb = Bsm + (c & (NSTAGE - 1)) * STAGE_H;
        #pragma unroll
        for (int kk = 0; kk < 32; kk += 16) {
            int kc = kk + (lane & 3) * 2;
            uint32_t af[4][4], bf[4][2];
            #pragma unroll
            for (int mi = 0; mi < 4; mi++) {
                int r = wm * 64 + mi * 16 + (lane >> 2);
                af[mi][0] = *(const uint32_t*)&Ab[r * GPITCH + kc];
                af[mi][1] = *(const uint32_t*)&Ab[(r + 8) * GPITCH + kc];
                af[mi][2] = *(const uint32_t*)&Ab[r * GPITCH + kc + 8];
                af[mi][3] = *(const uint32_t*)&Ab[(r + 8) * GPITCH + kc + 8];
            }
            #pragma unroll
            for (int ni = 0; ni < 4; ni++) {
                int n = wn * 32 + ni * 8 + (lane >> 2);
                bf[ni][0] = *(const uint32_t*)&Bb[n * GPITCH + kc];
                bf[ni][1] = *(const uint32_t*)&Bb[n * GPITCH + kc + 8];
            }
            #pragma unroll
            for (int mi = 0; mi < 4; mi++)
                #pragma unroll
                for (int ni = 0; ni < 4; ni++)
                    mma16816(acc[mi][ni], af[mi], bf[ni]);
        }
    }

    #pragma unroll
    for (int mi = 0; mi < 4; mi++) {
        #pragma unroll
        for (int ni = 0; ni < 4; ni++) {
            int col = n0 + wn * 32 + ni * 8 + (lane & 3) * 2;
            #pragma unroll
            for (int hh = 0; hh < 2; hh++) {
                int m = m0 + wm * 64 + mi * 16 + (lane >> 2) + hh * 8;
                float v0 = acc[mi][ni][hh * 2 + 0];
                float v1 = acc[mi][ni][hh * 2 + 1];
                if (EPI == 0) {
                    Cf[(size_t)m * N + col]     = v0;
                    Cf[(size_t)m * N + col + 1] = v1;
                } else if (EPI == 1) {
                    #pragma unroll
                    for (int e = 0; e < 2; e++) {
                        float v = (e ? v1 : v0) + bias[col + e];
                        v = 0.5f * v * (1.0f + erff(v * 0.70710678118654752f));
                        Cs[(size_t)m * KsegOut + col + e] = __float2bfloat16(v);
                    }
                } else {
                    size_t i0 = (size_t)m * N + col;
                    Cf[i0]     = (v0 + bias[col])     * ls[col]     + res[i0];
                    Cf[i0 + 1] = (v1 + bias[col + 1]) * ls[col + 1] + res[i0 + 1];
                }
            }
        }
    }
}

// ---------------------------------------------------------------------------
// dots[b,h,i,j] = scale[h] * sum_d q[b,i,h,d]*k[b,j,h,d]  (fp32, fused qkv)
// ---------------------------------------------------------------------------
__global__ __launch_bounds__(256) void dots_kernel(
    const float* __restrict__ qkv, const float* __restrict__ scale,
    float* __restrict__ dots)
{
    int bh = blockIdx.z;
    int b = bh / HH, h = bh % HH;
    int i0 = blockIdx.y * 64, j0 = blockIdx.x * 64;
    __shared__ float Qs[64][65];
    __shared__ float Ks[64][65];
    int tid = threadIdx.x, tx = tid & 15, ty = tid >> 4;

    #pragma unroll
    for (int v = 0; v < 4; v++) {
        int lin = tid + v * 256;
        int r = lin >> 4, c = (lin & 15) * 4;
        float4 qa = *(const float4*)&qkv[(size_t)(b * NN + i0 + r) * K3Q + h * DHD + c];
        Qs[r][c] = qa.x; Qs[r][c + 1] = qa.y; Qs[r][c + 2] = qa.z; Qs[r][c + 3] = qa.w;
        float4 ka = *(const float4*)&qkv[(size_t)(b * NN + j0 + r) * K3Q + 384 + h * DHD + c];
        Ks[r][c] = ka.x; Ks[r][c + 1] = ka.y; Ks[r][c + 2] = ka.z; Ks[r][c + 3] = ka.w;
    }
    __syncthreads();

    float acc[4][4] = {};
    #pragma unroll 8
    for (int d = 0; d < 64; d++) {
        float a[4], bb[4];
        #pragma unroll
        for (int i = 0; i < 4; i++) a[i] = Qs[ty * 4 + i][d];
        #pragma unroll
        for (int j = 0; j < 4; j++) bb[j] = Ks[tx * 4 + j][d];
        #pragma unroll
        for (int i = 0; i < 4; i++)
            #pragma unroll
            for (int j = 0; j < 4; j++)
                acc[i][j] = fmaf(a[i], bb[j], acc[i][j]);
    }

    float sc = scale[h];
    #pragma unroll
    for (int i = 0; i < 4; i++)
        #pragma unroll
        for (int j = 0; j < 4; j++)
            dots[((size_t)bh * NN + i0 + ty * 4 + i) * NN + j0 + tx * 4 + j] = acc[i][j] * sc;
}

// ---------------------------------------------------------------------------
// Fused pre-mix -> mask -> softmax -> post-mix (6-way interleaved reductions)
// ---------------------------------------------------------------------------
__global__ __launch_bounds__(256) void softmax_mix_kernel(
    const float* __restrict__ dots, const float* __restrict__ mp,
    const float* __restrict__ mq, float* __restrict__ attn)
{
    int b = blockIdx.x >> 8;
    int i = blockIdx.x & 255;
    int j = threadIdx.x;
    int lane = j & 31, wrp = j >> 5;

    __shared__ float smp[36], smq[36];
    __shared__ float red[8][6];
    if (j < 36) { smp[j] = mp[j]; smq[j] = mq[j]; }

    float raw[HH];
    #pragma unroll
    for (int h = 0; h < HH; h++)
        raw[h] = dots[(((size_t)(b * HH + h)) * NN + i) * NN + j];
    __syncthreads();

    float pm[HH];
    #pragma unroll
    for (int g = 0; g < HH; g++) {
        float s = 0.0f;
        #pragma unroll
        for (int h = 0; h < HH; h++) s = fmaf(raw[h], smp[h * HH + g], s);
        pm[g] = s;
    }
    if (j == i) {
        #pragma unroll
        for (int g = 0; g < HH; g++) pm[g] = -INFINITY;
    }

    float mx[HH];
    #pragma unroll
    for (int g = 0; g < HH; g++) mx[g] = pm[g];
    #pragma unroll
    for (int o = 16; o; o >>= 1)
        #pragma unroll
        for (int g = 0; g < HH; g++)
            mx[g] = fmaxf(mx[g], __shfl_xor_sync(0xffffffffu, mx[g], o));
    if (lane == 0)
        #pragma unroll
        for (int g = 0; g < HH; g++) red[wrp][g] = mx[g];
    __syncthreads();
    #pragma unroll
    for (int g = 0; g < HH; g++) {
        float m = red[0][g];
        #pragma unroll
        for (int w = 1; w < 8; w++) m = fmaxf(m, red[w][g]);
        mx[g] = m;
    }
    __syncthreads();

    float ex[HH], sm[HH];
    #pragma unroll
    for (int g = 0; g < HH; g++) { ex[g] = expf(pm[g] - mx[g]); sm[g] = ex[g]; }
    #pragma unroll
    for (int o = 16; o; o >>= 1)
        #pragma unroll
        for (int g = 0; g < HH; g++)
            sm[g] += __shfl_xor_sync(0xffffffffu, sm[g], o);
    if (lane == 0)
        #pragma unroll
        for (int g = 0; g < HH; g++) red[wrp][g] = sm[g];
    __syncthreads();
    float a[HH];
    #pragma unroll
    for (int g = 0; g < HH; g++) {
        float s = red[0][g];
        #pragma unroll
        for (int w = 1; w < 8; w++) s += red[w][g];
        a[g] = ex[g] / s;
    }

    #pragma unroll
    for (int g = 0; g < HH; g++) {
        float s = 0.0f;
        #pragma unroll
        for (int h = 0; h < HH; h++) s = fmaf(a[h], smq[h * HH + g], s);
        attn[(((size_t)(b * HH + g)) * NN + i) * NN + j] = s;
    }
}

// ---------------------------------------------------------------------------
// o[b,i,:] bf16 = sum_j attn[b,h,i,j] * v[b,j,h,d]
// ---------------------------------------------------------------------------
__global__ __launch_bounds__(256) void attnv_kernel(
    const float* __restrict__ attn, const float* __restrict__ qkv,
    __nv_bfloat16* __restrict__ op)
{
    int bh = blockIdx.y;
    int b = bh / HH, h = bh % HH;
    int i0 = blockIdx.x * 64;
    __shared__ float As[32][68];
    __shared__ float Vs[32][64];
    int tid = threadIdx.x, tx = tid & 15, ty = tid >> 4;
    float acc[4][4] = {};

    const float* abase = attn + (size_t)bh * NN * NN;
    const float* vbase = qkv + 768 + h * DHD;

    for (int j0 = 0; j0 < NN; j0 += 32) {
        #pragma unroll
        for (int v = 0; v < 2; v++) {
            int lin = tid + v * 256;
            int r = lin >> 3, c = (lin & 7) * 4;
            float4 a = *(const float4*)&abase[(size_t)(i0 + r) * NN + j0 + c];
            As[c + 0][r] = a.x; As[c + 1][r] = a.y; As[c + 2][r] = a.z; As[c + 3][r] = a.w;
        }
        #pragma unroll
        for (int v = 0; v < 2; v++) {
            int lin = tid + v * 256;
            int r = lin >> 4, c = (lin & 15) * 4;
            *(float4*)&Vs[r][c] =
                *(const float4*)&vbase[(size_t)(b * NN + j0 + r) * K3Q + c];
        }
        __syncthreads();
        #pragma unroll
        for (int jj = 0; jj < 32; jj++) {
            float4 a4 = *(const float4*)&As[jj][ty * 4];
            float4 b4 = *(const float4*)&Vs[jj][tx * 4];
            float a[4] = {a4.x, a4.y, a4.z, a4.w};
            float bb[4] = {b4.x, b4.y, b4.z, b4.w};
            #pragma unroll
            for (int i = 0; i < 4; i++)
                #pragma unroll
                for (int j = 0; j < 4; j++)
                    acc[i][j] = fmaf(a[i], bb[j], acc[i][j]);
        }
        __syncthreads();
    }

    #pragma unroll
    for (int i = 0; i < 4; i++) {
        size_t row = (size_t)(b * NN + i0 + ty * 4 + i);
        #pragma unroll
        for (int j = 0; j < 4; j++) {
            int col = h * DHD + tx * 4 + j;
            op[row * DIMD + col] = __float2bfloat16(acc[i][j]);
        }
    }
}

// ---------------------------------------------------------------------------
// Launch
// ---------------------------------------------------------------------------
extern "C" void kernel_launch(void* const* d_in, const int* in_sizes, int n_in,
                              void* d_out, int out_size)
{
    const float* x    = (const float*)d_in[0];
    const float* ln1g = (const float*)d_in[1];
    const float* ln1b = (const float*)d_in[2];
    const float* wq   = (const float*)d_in[3];
    const float* wkv  = (const float*)d_in[4];
    const float* scl  = (const float*)d_in[5];
    const float* mp   = (const float*)d_in[6];
    const float* mq   = (const float*)d_in[7];
    const float* wo   = (const float*)d_in[8];
    const float* bo   = (const float*)d_in[9];
    const float* ls1  = (const float*)d_in[10];
    const float* ln2g = (const float*)d_in[11];
    const float* ln2b = (const float*)d_in[12];
    const float* w1   = (const float*)d_in[13];
    const float* b1   = (const float*)d_in[14];
    const float* w2   = (const float*)d_in[15];
    const float* b2   = (const float*)d_in[16];
    const float* ls2  = (const float*)d_in[17];

    cudaFuncSetAttribute(tc_gemm<0>, cudaFuncAttributeMaxDynamicSharedMemorySize, GEMM_DSMEM);
    cudaFuncSetAttribute(tc_gemm<1>, cudaFuncAttributeMaxDynamicSharedMemorySize, GEMM_DSMEM);
    cudaFuncSetAttribute(tc_gemm<2>, cudaFuncAttributeMaxDynamicSharedMemorySize, GEMM_DSMEM);

    float *gx, *gqkv, *gdots, *gattn;
    __nv_bfloat16 *gyp, *gop, *ghp, *gwqkvp, *gwop, *gw1p, *gw2p;
    cudaGetSymbolAddress((void**)&gx,     g_x);
    cudaGetSymbolAddress((void**)&gqkv,   g_qkv);
    cudaGetSymbolAddress((void**)&gdots,  g_dots);
    cudaGetSymbolAddress((void**)&gattn,  g_attn);
    cudaGetSymbolAddress((void**)&gyp,    g_yp);
    cudaGetSymbolAddress((void**)&gop,    g_op);
    cudaGetSymbolAddress((void**)&ghp,    g_hp);
    cudaGetSymbolAddress((void**)&gwqkvp, g_wqkvp);
    cudaGetSymbolAddress((void**)&gwop,   g_wop);
    cudaGetSymbolAddress((void**)&gw1p,   g_w1p);
    cudaGetSymbolAddress((void**)&gw2p,   g_w2p);

    cudaMemcpyAsync(gx, x, (size_t)BN_ROWS * DIMD * sizeof(float),
                    cudaMemcpyDeviceToDevice, 0);

    // Weight transpose -> bf16 (row stride = K of the GEMM)
    for (int L = 0; L < DEPTH; L++) {
        wconv_kernel<<<dim3(384/32, 384/32), 256>>>(
            wq  + (size_t)L*DIMD*INNERD,   gwqkvp + (size_t)L*1152*DIMD, 384, 384,  0);
        wconv_kernel<<<dim3(768/32, 384/32), 256>>>(
            wkv + (size_t)L*DIMD*2*INNERD, gwqkvp + (size_t)L*1152*DIMD, 384, 768,  384);
        wconv_kernel<<<dim3(384/32, 384/32), 256>>>(
            wo  + (size_t)L*INNERD*DIMD,   gwop   + (size_t)L*384*DIMD,  384, 384,  0);
        wconv_kernel<<<dim3(1536/32, 384/32), 256>>>(
            w1  + (size_t)L*DIMD*MLPD,     gw1p   + (size_t)L*1536*DIMD, 384, 1536, 0);
        wconv_kernel<<<dim3(384/32, 1536/32), 256>>>(
            w2  + (size_t)L*MLPD*DIMD,     gw2p   + (size_t)L*384*MLPD,  1536, 384, 0);
    }

    for (int L = 0; L < DEPTH; L++) {
        const __nv_bfloat16* L_wqkvp = gwqkvp + (size_t)L*1152*DIMD;
        const __nv_bfloat16* L_wop   = gwop   + (size_t)L*384*DIMD;
        const __nv_bfloat16* L_w1p   = gw1p   + (size_t)L*1536*DIMD;
        const __nv_bfloat16* L_w2p   = gw2p   + (size_t)L*384*MLPD;

        // Attention
        ln_bf16_kernel<<<BN_ROWS, 128>>>(gx, ln1g + L*DIMD, ln1b + L*DIMD, gyp);
        tc_gemm<0><<<dim3(1152/128, BN_ROWS/128), 256, GEMM_DSMEM>>>(
            gyp, L_wqkvp, DIMD, 1152, DIMD/32, gqkv, nullptr, 0,
            nullptr, nullptr, nullptr);
        dots_kernel<<<dim3(NN/64, NN/64, BB*HH), 256>>>(gqkv, scl + L*HH, gdots);
        softmax_mix_kernel<<<BB*NN, 256>>>(gdots, mp + L*HH*HH, mq + L*HH*HH, gattn);
        attnv_kernel<<<dim3(NN/64, BB*HH), 256>>>(gattn, gqkv, gop);
        tc_gemm<2><<<dim3(384/128, BN_ROWS/128), 256, GEMM_DSMEM>>>(
            gop, L_wop, DIMD, 384, DIMD/32, gx, nullptr, 0,
            bo + L*DIMD, ls1 + L*DIMD, gx);

        // FFN
        ln_bf16_kernel<<<BN_ROWS, 128>>>(gx, ln2g + L*DIMD, ln2b + L*DIMD, gyp);
        tc_gemm<1><<<dim3(1536/128, BN_ROWS/128), 256, GEMM_DSMEM>>>(
            gyp, L_w1p, DIMD, 1536, DIMD/32, nullptr, ghp, MLPD,
            b1 + L*MLPD, nullptr, nullptr);
        tc_gemm<2><<<dim3(384/128, BN_ROWS/128), 256, GEMM_DSMEM>>>(
            ghp, L_w2p, MLPD, 384, MLPD/32, gx, nullptr, 0,
            b2 + L*DIMD, ls2 + L*DIMD, gx);
    }

    cudaMemcpyAsync(d_out, gx, (size_t)BN_ROWS * DIMD * sizeof(float),
                    cudaMemcpyDeviceToDevice, 0);
}

// round 12
// speedup vs baseline: 3.4369x; 1.2389x over previous
#include <cuda_runtime.h>
#include <cuda_bf16.h>
#include <math.h>
#include <stdint.h>

// Problem dims
#define BB   32
#define NN   256
#define DIMD 384
#define HH   6
#define DHD  64
#define MLPD 1536
#define DEPTH 12
#define INNERD 384
#define BN_ROWS (BB*NN)          // 8192
#define K3Q (3*DIMD)             // 1152 (qkv output cols)

// ---------------------------------------------------------------------------
// Device scratch
// ---------------------------------------------------------------------------
__device__ __align__(128) float g_x   [BN_ROWS*DIMD];
__device__ __align__(128) float g_qkv [BN_ROWS*K3Q];
__device__ __align__(128) float g_dots[(size_t)BB*HH*NN*NN];
__device__ __align__(128) __nv_bfloat16 g_attn[(size_t)BB*HH*NN*NN];
__device__ __align__(128) __nv_bfloat16 g_yp[(size_t)BN_ROWS*DIMD];
__device__ __align__(128) __nv_bfloat16 g_op[(size_t)BN_ROWS*DIMD];
__device__ __align__(128) __nv_bfloat16 g_hp[(size_t)BN_ROWS*MLPD];
__device__ __align__(128) __nv_bfloat16 g_wqkvp[(size_t)DEPTH*1152*DIMD];
__device__ __align__(128) __nv_bfloat16 g_wop  [(size_t)DEPTH*384 *DIMD];
__device__ __align__(128) __nv_bfloat16 g_w1p  [(size_t)DEPTH*1536*DIMD];
__device__ __align__(128) __nv_bfloat16 g_w2p  [(size_t)DEPTH*384 *MLPD];

// ---------------------------------------------------------------------------
// Helpers
// ---------------------------------------------------------------------------
__device__ __forceinline__ uint32_t cvta_s(const void* p) {
    uint32_t a;
    asm("{ .reg .u64 t; cvta.to.shared.u64 t, %1; cvt.u32.u64 %0, t; }"
        : "=r"(a) : "l"(p));
    return a;
}
#define CP_ASYNC16(dst, src) \
    asm volatile("cp.async.cg.shared.global [%0], [%1], 16;" :: "r"(dst), "l"(src))
#define CP_COMMIT()  asm volatile("cp.async.commit_group;")
#define CP_WAIT2()   asm volatile("cp.async.wait_group 2;" ::: "memory")

__device__ __forceinline__ void mma16816(float* d, const uint32_t* a, const uint32_t* b) {
    asm volatile(
        "mma.sync.aligned.m16n8k16.row.col.f32.bf16.bf16.f32 "
        "{%0,%1,%2,%3}, {%4,%5,%6,%7}, {%8,%9}, {%0,%1,%2,%3};\n"
        : "+f"(d[0]), "+f"(d[1]), "+f"(d[2]), "+f"(d[3])
        : "r"(a[0]), "r"(a[1]), "r"(a[2]), "r"(a[3]), "r"(b[0]), "r"(b[1]));
}

// ---------------------------------------------------------------------------
// Weight transpose to bf16: W[K,N] fp32 -> out[n][k] bf16 (row stride = K)
// ---------------------------------------------------------------------------
__global__ __launch_bounds__(256) void wconv_kernel(
    const float* __restrict__ W, __nv_bfloat16* __restrict__ out,
    int K, int N, int rowOff)
{
    __shared__ float tile[32][33];
    int k0 = blockIdx.y * 32, n0 = blockIdx.x * 32;
    int tx = threadIdx.x & 31, ty = threadIdx.x >> 5;
    #pragma unroll
    for (int i = 0; i < 4; i++) {
        int r = ty + i * 8;
        tile[r][tx] = W[(size_t)(k0 + r) * N + n0 + tx];
    }
    __syncthreads();
    #pragma unroll
    for (int i = 0; i < 4; i++) {
        int r = ty + i * 8;
        out[(size_t)(rowOff + n0 + r) * K + k0 + tx] = __float2bfloat16(tile[tx][r]);
    }
}

// ---------------------------------------------------------------------------
// LayerNorm -> plain bf16 output
// ---------------------------------------------------------------------------
__global__ __launch_bounds__(128) void ln_bf16_kernel(
    const float* __restrict__ x, const float* __restrict__ g,
    const float* __restrict__ b, __nv_bfloat16* __restrict__ yp)
{
    int row = blockIdx.x;
    int t = threadIdx.x;
    const float* xr = x + (size_t)row * DIMD;
    float v0 = xr[t], v1 = xr[t + 128], v2 = xr[t + 256];

    __shared__ float scratch[4];
    float s = v0 + v1 + v2;
    #pragma unroll
    for (int o = 16; o; o >>= 1) s += __shfl_xor_sync(0xffffffffu, s, o);
    if ((t & 31) == 0) scratch[t >> 5] = s;
    __syncthreads();
    s = scratch[0] + scratch[1] + scratch[2] + scratch[3];
    float mean = s * (1.0f / DIMD);

    float d0 = v0 - mean, d1 = v1 - mean, d2 = v2 - mean;
    float q = d0 * d0 + d1 * d1 + d2 * d2;
    __syncthreads();
    #pragma unroll
    for (int o = 16; o; o >>= 1) q += __shfl_xor_sync(0xffffffffu, q, o);
    if ((t & 31) == 0) scratch[t >> 5] = q;
    __syncthreads();
    q = scratch[0] + scratch[1] + scratch[2] + scratch[3];
    float rstd = rsqrtf(q * (1.0f / DIMD) + 1e-5f);

    __nv_bfloat16* yr = yp + (size_t)row * DIMD;
    yr[t]       = __float2bfloat16(d0 * rstd * g[t]       + b[t]);
    yr[t + 128] = __float2bfloat16(d1 * rstd * g[t + 128] + b[t + 128]);
    yr[t + 256] = __float2bfloat16(d2 * rstd * g[t + 256] + b[t + 256]);
}

// ---------------------------------------------------------------------------
// HMMA bf16 GEMM, 4-stage cp.async pipeline (dynamic smem, 80KB).
// 128x128x32 tile, 8 warps (64x32 each), scalar-LDS fragment loads.
// EPI 0: fp32 out. EPI 1: gelu(c+bias) -> bf16. EPI 2: (c+bias)*ls + res.
// ---------------------------------------------------------------------------
#define GPITCH 40
#define STAGE_H (128 * GPITCH)
#define NSTAGE 4
#define GEMM_DSMEM (2 * NSTAGE * STAGE_H * 2)   // 81920 B

template<int EPI>
__global__ __launch_bounds__(256) void tc_gemm(
    const __nv_bfloat16* __restrict__ A, const __nv_bfloat16* __restrict__ W,
    int K3, int N, int nchunks,
    float* __restrict__ Cf, __nv_bfloat16* __restrict__ Cs, int KsegOut,
    const float* __restrict__ bias, const float* __restrict__ ls,
    const float* __restrict__ res)
{
    extern __shared__ __nv_bfloat16 dsm[];
    __nv_bfloat16* Asm = dsm;
    __nv_bfloat16* Bsm = dsm + NSTAGE * STAGE_H;

    int tid = threadIdx.x, lane = tid & 31, wid = tid >> 5;
    __builtin_assume(tid < 256);
    int wm = wid & 1, wn = wid >> 1;
    int m0 = blockIdx.y * 128, n0 = blockIdx.x * 128;

    float acc[4][4][4] = {};

    auto load_chunk = [&](int c) {
        int buf = c & (NSTAGE - 1);
        int k0 = c * 32;
        #pragma unroll
        for (int rep = 0; rep < 2; rep++) {
            int u = tid + rep * 256;
            int row = u >> 2, q = u & 3;
            uint32_t da = cvta_s(&Asm[buf * STAGE_H + row * GPITCH + q * 8]);
            uint32_t db = cvta_s(&Bsm[buf * STAGE_H + row * GPITCH + q * 8]);
            CP_ASYNC16(da, A + (size_t)(m0 + row) * K3 + k0 + q * 8);
            CP_ASYNC16(db, W + (size_t)(n0 + row) * K3 + k0 + q * 8);
        }
        CP_COMMIT();
    };

    load_chunk(0);
    load_chunk(1);
    load_chunk(2);

    for (int c = 0; c < nchunks; c++) {
        CP_WAIT2();
        __syncthreads();
        if (c + 3 < nchunks) load_chunk(c + 3);
        else                 CP_COMMIT();

        const __nv_bfloat16* Ab = Asm + (c & (NSTAGE - 1)) * STAGE_H;
        const __nv_bfloat16* Bb = Bsm + (c & (NSTAGE - 1)) * STAGE_H;
        #pragma unroll
        for (int kk = 0; kk < 32; kk += 16) {
            int kc = kk + (lane & 3) * 2;
            uint32_t af[4][4], bf[4][2];
            #pragma unroll
            for (int mi = 0; mi < 4; mi++) {
                int r = wm * 64 + mi * 16 + (lane >> 2);
                af[mi][0] = *(const uint32_t*)&Ab[r * GPITCH + kc];
                af[mi][1] = *(const uint32_t*)&Ab[(r + 8) * GPITCH + kc];
                af[mi][2] = *(const uint32_t*)&Ab[r * GPITCH + kc + 8];
                af[mi][3] = *(const uint32_t*)&Ab[(r + 8) * GPITCH + kc + 8];
            }
            #pragma unroll
            for (int ni = 0; ni < 4; ni++) {
                int n = wn * 32 + ni * 8 + (lane >> 2);
                bf[ni][0] = *(const uint32_t*)&Bb[n * GPITCH + kc];
                bf[ni][1] = *(const uint32_t*)&Bb[n * GPITCH + kc + 8];
            }
            #pragma unroll
            for (int mi = 0; mi < 4; mi++)
                #pragma unroll
                for (int ni = 0; ni < 4; ni++)
                    mma16816(acc[mi][ni], af[mi], bf[ni]);
        }
    }

    #pragma unroll
    for (int mi = 0; mi < 4; mi++) {
        #pragma unroll
        for (int ni = 0; ni < 4; ni++) {
            int col = n0 + wn * 32 + ni * 8 + (lane & 3) * 2;
            #pragma unroll
            for (int hh = 0; hh < 2; hh++) {
                int m = m0 + wm * 64 + mi * 16 + (lane >> 2) + hh * 8;
                float v0 = acc[mi][ni][hh * 2 + 0];
                float v1 = acc[mi][ni][hh * 2 + 1];
                if (EPI == 0) {
                    Cf[(size_t)m * N + col]     = v0;
                    Cf[(size_t)m * N + col + 1] = v1;
                } else if (EPI == 1) {
                    #pragma unroll
                    for (int e = 0; e < 2; e++) {
                        float v = (e ? v1 : v0) + bias[col + e];
                        v = 0.5f * v * (1.0f + erff(v * 0.70710678118654752f));
                        Cs[(size_t)m * KsegOut + col + e] = __float2bfloat16(v);
                    }
                } else {
                    size_t i0 = (size_t)m * N + col;
                    Cf[i0]     = (v0 + bias[col])     * ls[col]     + res[i0];
                    Cf[i0 + 1] = (v1 + bias[col + 1]) * ls[col + 1] + res[i0 + 1];
                }
            }
        }
    }
}

// ---------------------------------------------------------------------------
// dots via HMMA: per z=(b,h) tile 128x128, K=64.
// q,k read fp32 from fused qkv, converted to bf16 in smem (pitch 72).
// grid (2, 2, 192). dots written fp32 (scaled).
// ---------------------------------------------------------------------------
#define DP 72    // halves pitch: row stride 36 words -> banks (4n+q) all distinct

__global__ __launch_bounds__(256) void dots_mma(
    const float* __restrict__ qkv, const float* __restrict__ scale,
    float* __restrict__ dots)
{
    __shared__ __nv_bfloat16 Qs[128 * DP];
    __shared__ __nv_bfloat16 Ks[128 * DP];

    int z = blockIdx.z;
    int b = z / HH, h = z % HH;
    int i0 = blockIdx.y * 128, j0 = blockIdx.x * 128;

    int tid = threadIdx.x, lane = tid & 31, wid = tid >> 5;
    __builtin_assume(tid < 256);
    int wm = wid & 1, wn = wid >> 1;

    // Load + convert: 128 rows x 64 fp32 each for Q and K (16 float4 per row)
    #pragma unroll
    for (int it = 0; it < 8; it++) {
        int u = tid + it * 256;
        int r = u >> 4, q = u & 15;
        float4 qa = *(const float4*)&qkv[(size_t)(b * NN + i0 + r) * K3Q + h * DHD + q * 4];
        float4 ka = *(const float4*)&qkv[(size_t)(b * NN + j0 + r) * K3Q + 384 + h * DHD + q * 4];
        __nv_bfloat162* qd = (__nv_bfloat162*)&Qs[r * DP + q * 4];
        __nv_bfloat162* kd = (__nv_bfloat162*)&Ks[r * DP + q * 4];
        qd[0] = __nv_bfloat162{__float2bfloat16(qa.x), __float2bfloat16(qa.y)};
        qd[1] = __nv_bfloat162{__float2bfloat16(qa.z), __float2bfloat16(qa.w)};
        kd[0] = __nv_bfloat162{__float2bfloat16(ka.x), __float2bfloat16(ka.y)};
        kd[1] = __nv_bfloat162{__float2bfloat16(ka.z), __float2bfloat16(ka.w)};
    }
    __syncthreads();

    float acc[4][4][4] = {};
    #pragma unroll
    for (int kk = 0; kk < 64; kk += 16) {
        int kc = kk + (lane & 3) * 2;
        uint32_t af[4][4], bf[4][2];
        #pragma unroll
        for (int mi = 0; mi < 4; mi++) {
            int r = wm * 64 + mi * 16 + (lane >> 2);
            af[mi][0] = *(const uint32_t*)&Qs[r * DP + kc];
            af[mi][1] = *(const uint32_t*)&Qs[(r + 8) * DP + kc];
            af[mi][2] = *(const uint32_t*)&Qs[r * DP + kc + 8];
            af[mi][3] = *(const uint32_t*)&Qs[(r + 8) * DP + kc + 8];
        }
        #pragma unroll
        for (int ni = 0; ni < 4; ni++) {
            int n = wn * 32 + ni * 8 + (lane >> 2);
            bf[ni][0] = *(const uint32_t*)&Ks[n * DP + kc];
            bf[ni][1] = *(const uint32_t*)&Ks[n * DP + kc + 8];
        }
        #pragma unroll
        for (int mi = 0; mi < 4; mi++)
            #pragma unroll
            for (int ni = 0; ni < 4; ni++)
                mma16816(acc[mi][ni], af[mi], bf[ni]);
    }

    float sc = scale[h];
    float* C = dots + (size_t)z * NN * NN;
    #pragma unroll
    for (int mi = 0; mi < 4; mi++)
        #pragma unroll
        for (int ni = 0; ni < 4; ni++) {
            int col = j0 + wn * 32 + ni * 8 + (lane & 3) * 2;
            #pragma unroll
            for (int hh = 0; hh < 2; hh++) {
                int m = i0 + wm * 64 + mi * 16 + (lane >> 2) + hh * 8;
                C[(size_t)m * NN + col]     = acc[mi][ni][hh * 2 + 0] * sc;
                C[(size_t)m * NN + col + 1] = acc[mi][ni][hh * 2 + 1] * sc;
            }
        }
}

// ---------------------------------------------------------------------------
// Fused pre-mix -> mask -> softmax -> post-mix; writes attn as bf16
// ---------------------------------------------------------------------------
__global__ __launch_bounds__(256) void softmax_mix_kernel(
    const float* __restrict__ dots, const float* __restrict__ mp,
    const float* __restrict__ mq, __nv_bfloat16* __restrict__ attn)
{
    int b = blockIdx.x >> 8;
    int i = blockIdx.x & 255;
    int j = threadIdx.x;
    int lane = j & 31, wrp = j >> 5;

    __shared__ float smp[36], smq[36];
    __shared__ float red[8][6];
    if (j < 36) { smp[j] = mp[j]; smq[j] = mq[j]; }

    float raw[HH];
    #pragma unroll
    for (int h = 0; h < HH; h++)
        raw[h] = dots[(((size_t)(b * HH + h)) * NN + i) * NN + j];
    __syncthreads();

    float pm[HH];
    #pragma unroll
    for (int g = 0; g < HH; g++) {
        float s = 0.0f;
        #pragma unroll
        for (int h = 0; h < HH; h++) s = fmaf(raw[h], smp[h * HH + g], s);
        pm[g] = s;
    }
    if (j == i) {
        #pragma unroll
        for (int g = 0; g < HH; g++) pm[g] = -INFINITY;
    }

    float mx[HH];
    #pragma unroll
    for (int g = 0; g < HH; g++) mx[g] = pm[g];
    #pragma unroll
    for (int o = 16; o; o >>= 1)
        #pragma unroll
        for (int g = 0; g < HH; g++)
            mx[g] = fmaxf(mx[g], __shfl_xor_sync(0xffffffffu, mx[g], o));
    if (lane == 0)
        #pragma unroll
        for (int g = 0; g < HH; g++) red[wrp][g] = mx[g];
    __syncthreads();
    #pragma unroll
    for (int g = 0; g < HH; g++) {
        float m = red[0][g];
        #pragma unroll
        for (int w = 1; w < 8; w++) m = fmaxf(m, red[w][g]);
        mx[g] = m;
    }
    __syncthreads();

    float ex[HH], sm[HH];
    #pragma unroll
    for (int g = 0; g < HH; g++) { ex[g] = expf(pm[g] - mx[g]); sm[g] = ex[g]; }
    #pragma unroll
    for (int o = 16; o; o >>= 1)
        #pragma unroll
        for (int g = 0; g < HH; g++)
            sm[g] += __shfl_xor_sync(0xffffffffu, sm[g], o);
    if (lane == 0)
        #pragma unroll
        for (int g = 0; g < HH; g++) red[wrp][g] = sm[g];
    __syncthreads();
    float a[HH];
    #pragma unroll
    for (int g = 0; g < HH; g++) {
        float s = red[0][g];
        #pragma unroll
        for (int w = 1; w < 8; w++) s += red[w][g];
        a[g] = ex[g] / s;
    }

    #pragma unroll
    for (int g = 0; g < HH; g++) {
        float s = 0.0f;
        #pragma unroll
        for (int h = 0; h < HH; h++) s = fmaf(a[h], smq[h * HH + g], s);
        attn[(((size_t)(b * HH + g)) * NN + i) * NN + j] = __float2bfloat16(s);
    }
}

// ---------------------------------------------------------------------------
// attn*V via HMMA: per z=(b,h): O[256,64] = attn[z](bf16) x v[z], K=256.
// Tile 128x64, 8 warps (4M x 2N, 32x32 each). V staged fp32 -> transposed bf16.
// grid (2, 192). Writes g_op bf16.
// ---------------------------------------------------------------------------
__global__ __launch_bounds__(256) void attnv_mma(
    const __nv_bfloat16* __restrict__ attn, const float* __restrict__ qkv,
    __nv_bfloat16* __restrict__ op)
{
    __shared__ __nv_bfloat16 As[128 * DP];     // attn tile, 18.4KB
    __shared__ float Vs32[64][68];             // V staging, 17.4KB
    __shared__ __nv_bfloat16 Vst[64 * DP];     // V^T bf16, 9.2KB

    int z = blockIdx.y;
    int b = z / HH, h = z % HH;
    int i0 = blockIdx.x * 128;

    int tid = threadIdx.x, lane = tid & 31, wid = tid >> 5;
    __builtin_assume(tid < 256);
    int wm = wid & 3, wn = wid >> 2;

    const __nv_bfloat16* abase = attn + (size_t)z * NN * NN;
    const float* vbase = qkv + 768 + h * DHD;

    float acc[2][4][4] = {};

    for (int c = 0; c < 4; c++) {
        int j0 = c * 64;
        // A: 128 rows x 64 bf16 (8 uint4 per row)
        #pragma unroll
        for (int it = 0; it < 4; it++) {
            int u = tid + it * 256;
            int r = u >> 3, q = u & 7;
            uint4 v = *(const uint4*)&abase[(size_t)(i0 + r) * NN + j0 + q * 8];
            *(uint4*)&As[r * DP + q * 8] = v;
        }
        // V: 64 rows (j) x 64 fp32, coalesced
        #pragma unroll
        for (int it = 0; it < 4; it++) {
            int u = tid + it * 256;
            int r = u >> 4, q = u & 15;
            *(float4*)&Vs32[r][q * 4] =
                *(const float4*)&vbase[(size_t)(b * NN + j0 + r) * K3Q + q * 4];
        }
        __syncthreads();
        // transpose-convert: Vst[d][j] = bf16(Vs32[j][d])
        #pragma unroll
        for (int it = 0; it < 8; it++) {
            int u = tid + it * 256;
            int d = u & 63, jp = u >> 6;
            __nv_bfloat162 p;
            p.x = __float2bfloat16(Vs32[2 * jp][d]);
            p.y = __float2bfloat16(Vs32[2 * jp + 1][d]);
            *(__nv_bfloat162*)&Vst[d * DP + jp * 2] = p;
        }
        __syncthreads();

        #pragma unroll
        for (int kk = 0; kk < 64; kk += 16) {
            int kc = kk + (lane & 3) * 2;
            uint32_t af[2][4], bf[4][2];
            #pragma unroll
            for (int mi = 0; mi < 2; mi++) {
                int r = wm * 32 + mi * 16 + (lane >> 2);
                af[mi][0] = *(const uint32_t*)&As[r * DP + kc];
                af[mi][1] = *(const uint32_t*)&As[(r + 8) * DP + kc];
                af[mi][2] = *(const uint32_t*)&As[r * DP + kc + 8];
                af[mi][3] = *(const uint32_t*)&As[(r + 8) * DP + kc + 8];
            }
            #pragma unroll
            for (int ni = 0; ni < 4; ni++) {
                int n = wn * 32 + ni * 8 + (lane >> 2);
                bf[ni][0] = *(const uint32_t*)&Vst[n * DP + kc];
                bf[ni][1] = *(const uint32_t*)&Vst[n * DP + kc + 8];
            }
            #pragma unroll
            for (int mi = 0; mi < 2; mi++)
                #pragma unroll
                for (int ni = 0; ni < 4; ni++)
                    mma16816(acc[mi][ni], af[mi], bf[ni]);
        }
        __syncthreads();
    }

    #pragma unroll
    for (int mi = 0; mi < 2; mi++)
        #pragma unroll
        for (int ni = 0; ni < 4; ni++) {
            int d0 = wn * 32 + ni * 8 + (lane & 3) * 2;
            #pragma unroll
            for (int hh = 0; hh < 2; hh++) {
                int i = i0 + wm * 32 + mi * 16 + (lane >> 2) + hh * 8;
                size_t row = (size_t)b * NN + i;
                op[row * DIMD + h * DHD + d0]     =
                    __float2bfloat16(acc[mi][ni][hh * 2 + 0]);
                op[row * DIMD + h * DHD + d0 + 1] =
                    __float2bfloat16(acc[mi][ni][hh * 2 + 1]);
            }
        }
}

// ---------------------------------------------------------------------------
// Launch
// ---------------------------------------------------------------------------
extern "C" void kernel_launch(void* const* d_in, const int* in_sizes, int n_in,
                              void* d_out, int out_size)
{
    const float* x    = (const float*)d_in[0];
    const float* ln1g = (const float*)d_in[1];
    const float* ln1b = (const float*)d_in[2];
    const float* wq   = (const float*)d_in[3];
    const float* wkv  = (const float*)d_in[4];
    const float* scl  = (const float*)d_in[5];
    const float* mp   = (const float*)d_in[6];
    const float* mq   = (const float*)d_in[7];
    const float* wo   = (const float*)d_in[8];
    const float* bo   = (const float*)d_in[9];
    const float* ls1  = (const float*)d_in[10];
    const float* ln2g = (const float*)d_in[11];
    const float* ln2b = (const float*)d_in[12];
    const float* w1   = (const float*)d_in[13];
    const float* b1   = (const float*)d_in[14];
    const float* w2   = (const float*)d_in[15];
    const float* b2   = (const float*)d_in[16];
    const float* ls2  = (const float*)d_in[17];

    cudaFuncSetAttribute(tc_gemm<0>, cudaFuncAttributeMaxDynamicSharedMemorySize, GEMM_DSMEM);
    cudaFuncSetAttribute(tc_gemm<1>, cudaFuncAttributeMaxDynamicSharedMemorySize, GEMM_DSMEM);
    cudaFuncSetAttribute(tc_gemm<2>, cudaFuncAttributeMaxDynamicSharedMemorySize, GEMM_DSMEM);

    float *gx, *gqkv, *gdots;
    __nv_bfloat16 *gattn, *gyp, *gop, *ghp, *gwqkvp, *gwop, *gw1p, *gw2p;
    cudaGetSymbolAddress((void**)&gx,     g_x);
    cudaGetSymbolAddress((void**)&gqkv,   g_qkv);
    cudaGetSymbolAddress((void**)&gdots,  g_dots);
    cudaGetSymbolAddress((void**)&gattn,  g_attn);
    cudaGetSymbolAddress((void**)&gyp,    g_yp);
    cudaGetSymbolAddress((void**)&gop,    g_op);
    cudaGetSymbolAddress((void**)&ghp,    g_hp);
    cudaGetSymbolAddress((void**)&gwqkvp, g_wqkvp);
    cudaGetSymbolAddress((void**)&gwop,   g_wop);
    cudaGetSymbolAddress((void**)&gw1p,   g_w1p);
    cudaGetSymbolAddress((void**)&gw2p,   g_w2p);

    cudaMemcpyAsync(gx, x, (size_t)BN_ROWS * DIMD * sizeof(float),
                    cudaMemcpyDeviceToDevice, 0);

    // Weight transpose -> bf16 (row stride = K of the GEMM)
    for (int L = 0; L < DEPTH; L++) {
        wconv_kernel<<<dim3(384/32, 384/32), 256>>>(
            wq  + (size_t)L*DIMD*INNERD,   gwqkvp + (size_t)L*1152*DIMD, 384, 384,  0);
        wconv_kernel<<<dim3(768/32, 384/32), 256>>>(
            wkv + (size_t)L*DIMD*2*INNERD, gwqkvp + (size_t)L*1152*DIMD, 384, 768,  384);
        wconv_kernel<<<dim3(384/32, 384/32), 256>>>(
            wo  + (size_t)L*INNERD*DIMD,   gwop   + (size_t)L*384*DIMD,  384, 384,  0);
        wconv_kernel<<<dim3(1536/32, 384/32), 256>>>(
            w1  + (size_t)L*DIMD*MLPD,     gw1p   + (size_t)L*1536*DIMD, 384, 1536, 0);
        wconv_kernel<<<dim3(384/32, 1536/32), 256>>>(
            w2  + (size_t)L*MLPD*DIMD,     gw2p   + (size_t)L*384*MLPD,  1536, 384, 0);
    }

    for (int L = 0; L < DEPTH; L++) {
        const __nv_bfloat16* L_wqkvp = gwqkvp + (size_t)L*1152*DIMD;
        const __nv_bfloat16* L_wop   = gwop   + (size_t)L*384*DIMD;
        const __nv_bfloat16* L_w1p   = gw1p   + (size_t)L*1536*DIMD;
        const __nv_bfloat16* L_w2p   = gw2p   + (size_t)L*384*MLPD;

        // Attention
        ln_bf16_kernel<<<BN_ROWS, 128>>>(gx, ln1g + L*DIMD, ln1b + L*DIMD, gyp);
        tc_gemm<0><<<dim3(1152/128, BN_ROWS/128), 256, GEMM_DSMEM>>>(
            gyp, L_wqkvp, DIMD, 1152, DIMD/32, gqkv, nullptr, 0,
            nullptr, nullptr, nullptr);
        dots_mma<<<dim3(2, 2, BB*HH), 256>>>(gqkv, scl + L*HH, gdots);
        softmax_mix_kernel<<<BB*NN, 256>>>(gdots, mp + L*HH*HH, mq + L*HH*HH, gattn);
        attnv_mma<<<dim3(2, BB*HH), 256>>>(gattn, gqkv, gop);
        tc_gemm<2><<<dim3(384/128, BN_ROWS/128), 256, GEMM_DSMEM>>>(
            gop, L_wop, DIMD, 384, DIMD/32, gx, nullptr, 0,
            bo + L*DIMD, ls1 + L*DIMD, gx);

        // FFN
        ln_bf16_kernel<<<BN_ROWS, 128>>>(gx, ln2g + L*DIMD, ln2b + L*DIMD, gyp);
        tc_gemm<1><<<dim3(1536/128, BN_ROWS/128), 256, GEMM_DSMEM>>>(
            gyp, L_w1p, DIMD, 1536, DIMD/32, nullptr, ghp, MLPD,
            b1 + L*MLPD, nullptr, nullptr);
        tc_gemm<2><<<dim3(384/128, BN_ROWS/128), 256, GEMM_DSMEM>>>(
            ghp, L_w2p, MLPD, 384, MLPD/32, gx, nullptr, 0,
            b2 + L*DIMD, ls2 + L*DIMD, gx);
    }

    cudaMemcpyAsync(d_out, gx, (size_t)BN_ROWS * DIMD * sizeof(float),
                    cudaMemcpyDeviceToDevice, 0);
}

// round 13
// speedup vs baseline: 3.4947x; 1.0168x over previous
#include <cuda_runtime.h>
#include <cuda_bf16.h>
#include <math.h>
#include <stdint.h>

// Problem dims
#define BB   32
#define NN   256
#define DIMD 384
#define HH   6
#define DHD  64
#define MLPD 1536
#define DEPTH 12
#define INNERD 384
#define BN_ROWS (BB*NN)          // 8192
#define K3Q (3*DIMD)             // 1152 (qkv output cols)

// ---------------------------------------------------------------------------
// Device scratch
// ---------------------------------------------------------------------------
__device__ __align__(128) float g_x   [BN_ROWS*DIMD];
__device__ __align__(128) float g_dots[(size_t)BB*HH*NN*NN];
__device__ __align__(128) __nv_bfloat16 g_qkv [(size_t)BN_ROWS*K3Q];
__device__ __align__(128) __nv_bfloat16 g_attn[(size_t)BB*HH*NN*NN];
__device__ __align__(128) __nv_bfloat16 g_yp[(size_t)BN_ROWS*DIMD];
__device__ __align__(128) __nv_bfloat16 g_op[(size_t)BN_ROWS*DIMD];
__device__ __align__(128) __nv_bfloat16 g_hp[(size_t)BN_ROWS*MLPD];
__device__ __align__(128) __nv_bfloat16 g_wqkvp[(size_t)DEPTH*1152*DIMD];
__device__ __align__(128) __nv_bfloat16 g_wop  [(size_t)DEPTH*384 *DIMD];
__device__ __align__(128) __nv_bfloat16 g_w1p  [(size_t)DEPTH*1536*DIMD];
__device__ __align__(128) __nv_bfloat16 g_w2p  [(size_t)DEPTH*384 *MLPD];

// ---------------------------------------------------------------------------
// Helpers
// ---------------------------------------------------------------------------
__device__ __forceinline__ uint32_t cvta_s(const void* p) {
    uint32_t a;
    asm("{ .reg .u64 t; cvta.to.shared.u64 t, %1; cvt.u32.u64 %0, t; }"
        : "=r"(a) : "l"(p));
    return a;
}
#define CP_ASYNC16(dst, src) \
    asm volatile("cp.async.cg.shared.global [%0], [%1], 16;" :: "r"(dst), "l"(src))
#define CP_COMMIT()  asm volatile("cp.async.commit_group;")
#define CP_WAIT2()   asm volatile("cp.async.wait_group 2;" ::: "memory")

__device__ __forceinline__ void mma16816(float* d, const uint32_t* a, const uint32_t* b) {
    asm volatile(
        "mma.sync.aligned.m16n8k16.row.col.f32.bf16.bf16.f32 "
        "{%0,%1,%2,%3}, {%4,%5,%6,%7}, {%8,%9}, {%0,%1,%2,%3};\n"
        : "+f"(d[0]), "+f"(d[1]), "+f"(d[2]), "+f"(d[3])
        : "r"(a[0]), "r"(a[1]), "r"(a[2]), "r"(a[3]), "r"(b[0]), "r"(b[1]));
}

// ---------------------------------------------------------------------------
// Batched weight transpose to bf16: per layer z, W[K,N] fp32 -> out[n][k] bf16
// ---------------------------------------------------------------------------
__global__ __launch_bounds__(256) void wconv_kernel(
    const float* __restrict__ W, __nv_bfloat16* __restrict__ out,
    int K, int N, int rowOff, size_t wStride, size_t oStride)
{
    const float* Wl = W + (size_t)blockIdx.z * wStride;
    __nv_bfloat16* ol = out + (size_t)blockIdx.z * oStride;

    __shared__ float tile[32][33];
    int k0 = blockIdx.y * 32, n0 = blockIdx.x * 32;
    int tx = threadIdx.x & 31, ty = threadIdx.x >> 5;
    #pragma unroll
    for (int i = 0; i < 4; i++) {
        int r = ty + i * 8;
        tile[r][tx] = Wl[(size_t)(k0 + r) * N + n0 + tx];
    }
    __syncthreads();
    #pragma unroll
    for (int i = 0; i < 4; i++) {
        int r = ty + i * 8;
        ol[(size_t)(rowOff + n0 + r) * K + k0 + tx] = __float2bfloat16(tile[tx][r]);
    }
}

// ---------------------------------------------------------------------------
// LayerNorm -> plain bf16 output
// ---------------------------------------------------------------------------
__global__ __launch_bounds__(128) void ln_bf16_kernel(
    const float* __restrict__ x, const float* __restrict__ g,
    const float* __restrict__ b, __nv_bfloat16* __restrict__ yp)
{
    int row = blockIdx.x;
    int t = threadIdx.x;
    const float* xr = x + (size_t)row * DIMD;
    float v0 = xr[t], v1 = xr[t + 128], v2 = xr[t + 256];

    __shared__ float scratch[4];
    float s = v0 + v1 + v2;
    #pragma unroll
    for (int o = 16; o; o >>= 1) s += __shfl_xor_sync(0xffffffffu, s, o);
    if ((t & 31) == 0) scratch[t >> 5] = s;
    __syncthreads();
    s = scratch[0] + scratch[1] + scratch[2] + scratch[3];
    float mean = s * (1.0f / DIMD);

    float d0 = v0 - mean, d1 = v1 - mean, d2 = v2 - mean;
    float q = d0 * d0 + d1 * d1 + d2 * d2;
    __syncthreads();
    #pragma unroll
    for (int o = 16; o; o >>= 1) q += __shfl_xor_sync(0xffffffffu, q, o);
    if ((t & 31) == 0) scratch[t >> 5] = q;
    __syncthreads();
    q = scratch[0] + scratch[1] + scratch[2] + scratch[3];
    float rstd = rsqrtf(q * (1.0f / DIMD) + 1e-5f);

    __nv_bfloat16* yr = yp + (size_t)row * DIMD;
    yr[t]       = __float2bfloat16(d0 * rstd * g[t]       + b[t]);
    yr[t + 128] = __float2bfloat16(d1 * rstd * g[t + 128] + b[t + 128]);
    yr[t + 256] = __float2bfloat16(d2 * rstd * g[t + 256] + b[t + 256]);
}

// ---------------------------------------------------------------------------
// HMMA bf16 GEMM, 4-stage cp.async pipeline (dynamic smem, 80KB).
// 128x128x32 tile, 8 warps (64x32 each), scalar-LDS fragment loads.
// EPI 1: gelu(c+bias) -> bf16 (stride KsegOut).
// EPI 2: (c+bias)*ls + res -> fp32.
// EPI 3: plain bf16 out (stride N).
// ---------------------------------------------------------------------------
#define GPITCH 40
#define STAGE_H (128 * GPITCH)
#define NSTAGE 4
#define GEMM_DSMEM (2 * NSTAGE * STAGE_H * 2)   // 81920 B

template<int EPI>
__global__ __launch_bounds__(256) void tc_gemm(
    const __nv_bfloat16* __restrict__ A, const __nv_bfloat16* __restrict__ W,
    int K3, int N, int nchunks,
    float* __restrict__ Cf, __nv_bfloat16* __restrict__ Cs, int KsegOut,
    const float* __restrict__ bias, const float* __restrict__ ls,
    const float* __restrict__ res)
{
    extern __shared__ __nv_bfloat16 dsm[];
    __nv_bfloat16* Asm = dsm;
    __nv_bfloat16* Bsm = dsm + NSTAGE * STAGE_H;

    int tid = threadIdx.x, lane = tid & 31, wid = tid >> 5;
    __builtin_assume(tid < 256);
    int wm = wid & 1, wn = wid >> 1;
    int m0 = blockIdx.y * 128, n0 = blockIdx.x * 128;

    float acc[4][4][4] = {};

    auto load_chunk = [&](int c) {
        int buf = c & (NSTAGE - 1);
        int k0 = c * 32;
        #pragma unroll
        for (int rep = 0; rep < 2; rep++) {
            int u = tid + rep * 256;
            int row = u >> 2, q = u & 3;
            uint32_t da = cvta_s(&Asm[buf * STAGE_H + row * GPITCH + q * 8]);
            uint32_t db = cvta_s(&Bsm[buf * STAGE_H + row * GPITCH + q * 8]);
            CP_ASYNC16(da, A + (size_t)(m0 + row) * K3 + k0 + q * 8);
            CP_ASYNC16(db, W + (size_t)(n0 + row) * K3 + k0 + q * 8);
        }
        CP_COMMIT();
    };

    load_chunk(0);
    load_chunk(1);
    load_chunk(2);

    for (int c = 0; c < nchunks; c++) {
        CP_WAIT2();
        __syncthreads();
        if (c + 3 < nchunks) load_chunk(c + 3);
        else                 CP_COMMIT();

        const __nv_bfloat16* Ab = Asm + (c & (NSTAGE - 1)) * STAGE_H;
        const __nv_bfloat16* Bb = Bsm + (c & (NSTAGE - 1)) * STAGE_H;
        #pragma unroll
        for (int kk = 0; kk < 32; kk += 16) {
            int kc = kk + (lane & 3) * 2;
            uint32_t af[4][4], bf[4][2];
            #pragma unroll
            for (int mi = 0; mi < 4; mi++) {
                int r = wm * 64 + mi * 16 + (lane >> 2);
                af[mi][0] = *(const uint32_t*)&Ab[r * GPITCH + kc];
                af[mi][1] = *(const uint32_t*)&Ab[(r + 8) * GPITCH + kc];
                af[mi][2] = *(const uint32_t*)&Ab[r * GPITCH + kc + 8];
                af[mi][3] = *(const uint32_t*)&Ab[(r + 8) * GPITCH + kc + 8];
            }
            #pragma unroll
            for (int ni = 0; ni < 4; ni++) {
                int n = wn * 32 + ni * 8 + (lane >> 2);
                bf[ni][0] = *(const uint32_t*)&Bb[n * GPITCH + kc];
                bf[ni][1] = *(const uint32_t*)&Bb[n * GPITCH + kc + 8];
            }
            #pragma unroll
            for (int mi = 0; mi < 4; mi++)
                #pragma unroll
                for (int ni = 0; ni < 4; ni++)
                    mma16816(acc[mi][ni], af[mi], bf[ni]);
        }
    }

    #pragma unroll
    for (int mi = 0; mi < 4; mi++) {
        #pragma unroll
        for (int ni = 0; ni < 4; ni++) {
            int col = n0 + wn * 32 + ni * 8 + (lane & 3) * 2;
            #pragma unroll
            for (int hh = 0; hh < 2; hh++) {
                int m = m0 + wm * 64 + mi * 16 + (lane >> 2) + hh * 8;
                float v0 = acc[mi][ni][hh * 2 + 0];
                float v1 = acc[mi][ni][hh * 2 + 1];
                if (EPI == 1) {
                    #pragma unroll
                    for (int e = 0; e < 2; e++) {
                        float v = (e ? v1 : v0) + bias[col + e];
                        v = 0.5f * v * (1.0f + erff(v * 0.70710678118654752f));
                        Cs[(size_t)m * KsegOut + col + e] = __float2bfloat16(v);
                    }
                } else if (EPI == 2) {
                    size_t i0 = (size_t)m * N + col;
                    Cf[i0]     = (v0 + bias[col])     * ls[col]     + res[i0];
                    Cf[i0 + 1] = (v1 + bias[col + 1]) * ls[col + 1] + res[i0 + 1];
                } else {   // EPI == 3: plain bf16
                    Cs[(size_t)m * N + col]     = __float2bfloat16(v0);
                    Cs[(size_t)m * N + col + 1] = __float2bfloat16(v1);
                }
            }
        }
    }
}

// ---------------------------------------------------------------------------
// dots via HMMA: per z=(b,h) tile 128x128, K=64. q,k bf16 from fused qkv.
// grid (2, 2, 192). dots written fp32 (scaled).
// ---------------------------------------------------------------------------
#define DP 72    // halves pitch

__global__ __launch_bounds__(256) void dots_mma(
    const __nv_bfloat16* __restrict__ qkv, const float* __restrict__ scale,
    float* __restrict__ dots)
{
    __shared__ __nv_bfloat16 Qs[128 * DP];
    __shared__ __nv_bfloat16 Ks[128 * DP];

    int z = blockIdx.z;
    int b = z / HH, h = z % HH;
    int i0 = blockIdx.y * 128, j0 = blockIdx.x * 128;

    int tid = threadIdx.x, lane = tid & 31, wid = tid >> 5;
    __builtin_assume(tid < 256);
    int wm = wid & 1, wn = wid >> 1;

    // Copy 128 rows x 64 halves (8 uint4 per row) for Q and K
    #pragma unroll
    for (int it = 0; it < 4; it++) {
        int u = tid + it * 256;
        int r = u >> 3, q = u & 7;
        *(uint4*)&Qs[r * DP + q * 8] =
            *(const uint4*)&qkv[(size_t)(b * NN + i0 + r) * K3Q + h * DHD + q * 8];
        *(uint4*)&Ks[r * DP + q * 8] =
            *(const uint4*)&qkv[(size_t)(b * NN + j0 + r) * K3Q + 384 + h * DHD + q * 8];
    }
    __syncthreads();

    float acc[4][4][4] = {};
    #pragma unroll
    for (int kk = 0; kk < 64; kk += 16) {
        int kc = kk + (lane & 3) * 2;
        uint32_t af[4][4], bf[4][2];
        #pragma unroll
        for (int mi = 0; mi < 4; mi++) {
            int r = wm * 64 + mi * 16 + (lane >> 2);
            af[mi][0] = *(const uint32_t*)&Qs[r * DP + kc];
            af[mi][1] = *(const uint32_t*)&Qs[(r + 8) * DP + kc];
            af[mi][2] = *(const uint32_t*)&Qs[r * DP + kc + 8];
            af[mi][3] = *(const uint32_t*)&Qs[(r + 8) * DP + kc + 8];
        }
        #pragma unroll
        for (int ni = 0; ni < 4; ni++) {
            int n = wn * 32 + ni * 8 + (lane >> 2);
            bf[ni][0] = *(const uint32_t*)&Ks[n * DP + kc];
            bf[ni][1] = *(const uint32_t*)&Ks[n * DP + kc + 8];
        }
        #pragma unroll
        for (int mi = 0; mi < 4; mi++)
            #pragma unroll
            for (int ni = 0; ni < 4; ni++)
                mma16816(acc[mi][ni], af[mi], bf[ni]);
    }

    float sc = scale[h];
    float* C = dots + (size_t)z * NN * NN;
    #pragma unroll
    for (int mi = 0; mi < 4; mi++)
        #pragma unroll
        for (int ni = 0; ni < 4; ni++) {
            int col = j0 + wn * 32 + ni * 8 + (lane & 3) * 2;
            #pragma unroll
            for (int hh = 0; hh < 2; hh++) {
                int m = i0 + wm * 64 + mi * 16 + (lane >> 2) + hh * 8;
                C[(size_t)m * NN + col]     = acc[mi][ni][hh * 2 + 0] * sc;
                C[(size_t)m * NN + col + 1] = acc[mi][ni][hh * 2 + 1] * sc;
            }
        }
}

// ---------------------------------------------------------------------------
// Fused pre-mix -> mask -> softmax -> post-mix; writes attn as bf16
// ---------------------------------------------------------------------------
__global__ __launch_bounds__(256) void softmax_mix_kernel(
    const float* __restrict__ dots, const float* __restrict__ mp,
    const float* __restrict__ mq, __nv_bfloat16* __restrict__ attn)
{
    int b = blockIdx.x >> 8;
    int i = blockIdx.x & 255;
    int j = threadIdx.x;
    int lane = j & 31, wrp = j >> 5;

    __shared__ float smp[36], smq[36];
    __shared__ float red[8][6];
    if (j < 36) { smp[j] = mp[j]; smq[j] = mq[j]; }

    float raw[HH];
    #pragma unroll
    for (int h = 0; h < HH; h++)
        raw[h] = dots[(((size_t)(b * HH + h)) * NN + i) * NN + j];
    __syncthreads();

    float pm[HH];
    #pragma unroll
    for (int g = 0; g < HH; g++) {
        float s = 0.0f;
        #pragma unroll
        for (int h = 0; h < HH; h++) s = fmaf(raw[h], smp[h * HH + g], s);
        pm[g] = s;
    }
    if (j == i) {
        #pragma unroll
        for (int g = 0; g < HH; g++) pm[g] = -INFINITY;
    }

    float mx[HH];
    #pragma unroll
    for (int g = 0; g < HH; g++) mx[g] = pm[g];
    #pragma unroll
    for (int o = 16; o; o >>= 1)
        #pragma unroll
        for (int g = 0; g < HH; g++)
            mx[g] = fmaxf(mx[g], __shfl_xor_sync(0xffffffffu, mx[g], o));
    if (lane == 0)
        #pragma unroll
        for (int g = 0; g < HH; g++) red[wrp][g] = mx[g];
    __syncthreads();
    #pragma unroll
    for (int g = 0; g < HH; g++) {
        float m = red[0][g];
        #pragma unroll
        for (int w = 1; w < 8; w++) m = fmaxf(m, red[w][g]);
        mx[g] = m;
    }
    __syncthreads();

    float ex[HH], sm[HH];
    #pragma unroll
    for (int g = 0; g < HH; g++) { ex[g] = expf(pm[g] - mx[g]); sm[g] = ex[g]; }
    #pragma unroll
    for (int o = 16; o; o >>= 1)
        #pragma unroll
        for (int g = 0; g < HH; g++)
            sm[g] += __shfl_xor_sync(0xffffffffu, sm[g], o);
    if (lane == 0)
        #pragma unroll
        for (int g = 0; g < HH; g++) red[wrp][g] = sm[g];
    __syncthreads();
    float a[HH];
    #pragma unroll
    for (int g = 0; g < HH; g++) {
        float s = red[0][g];
        #pragma unroll
        for (int w = 1; w < 8; w++) s += red[w][g];
        a[g] = ex[g] / s;
    }

    #pragma unroll
    for (int g = 0; g < HH; g++) {
        float s = 0.0f;
        #pragma unroll
        for (int h = 0; h < HH; h++) s = fmaf(a[h], smq[h * HH + g], s);
        attn[(((size_t)(b * HH + g)) * NN + i) * NN + j] = __float2bfloat16(s);
    }
}

// ---------------------------------------------------------------------------
// attn*V via HMMA: per z=(b,h): O[256,64] = attn[z](bf16) x v[z](bf16), K=256.
// Tile 128x64, 8 warps (4M x 2N, 32x32 each). V transposed in smem.
// grid (2, 192). Writes g_op bf16.
// ---------------------------------------------------------------------------
__global__ __launch_bounds__(256) void attnv_mma(
    const __nv_bfloat16* __restrict__ attn, const __nv_bfloat16* __restrict__ qkv,
    __nv_bfloat16* __restrict__ op)
{
    __shared__ __nv_bfloat16 As[128 * DP];     // attn tile
    __shared__ __nv_bfloat16 Vs16[64][DP];     // V staging [j][d]
    __shared__ __nv_bfloat16 Vst[64 * DP];     // V^T [d][j]

    int z = blockIdx.y;
    int b = z / HH, h = z % HH;
    int i0 = blockIdx.x * 128;

    int tid = threadIdx.x, lane = tid & 31, wid = tid >> 5;
    __builtin_assume(tid < 256);
    int wm = wid & 3, wn = wid >> 2;

    const __nv_bfloat16* abase = attn + (size_t)z * NN * NN;
    const __nv_bfloat16* vbase = qkv + 768 + h * DHD;

    float acc[2][4][4] = {};

    for (int c = 0; c < 4; c++) {
        int j0 = c * 64;
        // A: 128 rows x 64 bf16 (8 uint4 per row)
        #pragma unroll
        for (int it = 0; it < 4; it++) {
            int u = tid + it * 256;
            int r = u >> 3, q = u & 7;
            *(uint4*)&As[r * DP + q * 8] =
                *(const uint4*)&abase[(size_t)(i0 + r) * NN + j0 + q * 8];
        }
        // V: 64 rows (j) x 64 bf16
        #pragma unroll
        for (int it = 0; it < 2; it++) {
            int u = tid + it * 256;
            int r = u >> 3, q = u & 7;
            *(uint4*)&Vs16[r][q * 8] =
                *(const uint4*)&vbase[(size_t)(b * NN + j0 + r) * K3Q + q * 8];
        }
        __syncthreads();
        // transpose: Vst[d][j] = Vs16[j][d]
        #pragma unroll
        for (int it = 0; it < 8; it++) {
            int u = tid + it * 256;
            int d = u & 63, jp = u >> 6;
            __nv_bfloat162 p;
            p.x = Vs16[2 * jp][d];
            p.y = Vs16[2 * jp + 1][d];
            *(__nv_bfloat162*)&Vst[d * DP + jp * 2] = p;
        }
        __syncthreads();

        #pragma unroll
        for (int kk = 0; kk < 64; kk += 16) {
            int kc = kk + (lane & 3) * 2;
            uint32_t af[2][4], bf[4][2];
            #pragma unroll
            for (int mi = 0; mi < 2; mi++) {
                int r = wm * 32 + mi * 16 + (lane >> 2);
                af[mi][0] = *(const uint32_t*)&As[r * DP + kc];
                af[mi][1] = *(const uint32_t*)&As[(r + 8) * DP + kc];
                af[mi][2] = *(const uint32_t*)&As[r * DP + kc + 8];
                af[mi][3] = *(const uint32_t*)&As[(r + 8) * DP + kc + 8];
            }
            #pragma unroll
            for (int ni = 0; ni < 4; ni++) {
                int n = wn * 32 + ni * 8 + (lane >> 2);
                bf[ni][0] = *(const uint32_t*)&Vst[n * DP + kc];
                bf[ni][1] = *(const uint32_t*)&Vst[n * DP + kc + 8];
            }
            #pragma unroll
            for (int mi = 0; mi < 2; mi++)
                #pragma unroll
                for (int ni = 0; ni < 4; ni++)
                    mma16816(acc[mi][ni], af[mi], bf[ni]);
        }
        __syncthreads();
    }

    #pragma unroll
    for (int mi = 0; mi < 2; mi++)
        #pragma unroll
        for (int ni = 0; ni < 4; ni++) {
            int d0 = wn * 32 + ni * 8 + (lane & 3) * 2;
            #pragma unroll
            for (int hh = 0; hh < 2; hh++) {
                int i = i0 + wm * 32 + mi * 16 + (lane >> 2) + hh * 8;
                size_t row = (size_t)b * NN + i;
                op[row * DIMD + h * DHD + d0]     =
                    __float2bfloat16(acc[mi][ni][hh * 2 + 0]);
                op[row * DIMD + h * DHD + d0 + 1] =
                    __float2bfloat16(acc[mi][ni][hh * 2 + 1]);
            }
        }
}

// ---------------------------------------------------------------------------
// Launch
// ---------------------------------------------------------------------------
extern "C" void kernel_launch(void* const* d_in, const int* in_sizes, int n_in,
                              void* d_out, int out_size)
{
    const float* x    = (const float*)d_in[0];
    const float* ln1g = (const float*)d_in[1];
    const float* ln1b = (const float*)d_in[2];
    const float* wq   = (const float*)d_in[3];
    const float* wkv  = (const float*)d_in[4];
    const float* scl  = (const float*)d_in[5];
    const float* mp   = (const float*)d_in[6];
    const float* mq   = (const float*)d_in[7];
    const float* wo   = (const float*)d_in[8];
    const float* bo   = (const float*)d_in[9];
    const float* ls1  = (const float*)d_in[10];
    const float* ln2g = (const float*)d_in[11];
    const float* ln2b = (const float*)d_in[12];
    const float* w1   = (const float*)d_in[13];
    const float* b1   = (const float*)d_in[14];
    const float* w2   = (const float*)d_in[15];
    const float* b2   = (const float*)d_in[16];
    const float* ls2  = (const float*)d_in[17];

    cudaFuncSetAttribute(tc_gemm<1>, cudaFuncAttributeMaxDynamicSharedMemorySize, GEMM_DSMEM);
    cudaFuncSetAttribute(tc_gemm<2>, cudaFuncAttributeMaxDynamicSharedMemorySize, GEMM_DSMEM);
    cudaFuncSetAttribute(tc_gemm<3>, cudaFuncAttributeMaxDynamicSharedMemorySize, GEMM_DSMEM);

    float *gx, *gdots;
    __nv_bfloat16 *gqkv, *gattn, *gyp, *gop, *ghp, *gwqkvp, *gwop, *gw1p, *gw2p;
    cudaGetSymbolAddress((void**)&gx,     g_x);
    cudaGetSymbolAddress((void**)&gqkv,   g_qkv);
    cudaGetSymbolAddress((void**)&gdots,  g_dots);
    cudaGetSymbolAddress((void**)&gattn,  g_attn);
    cudaGetSymbolAddress((void**)&gyp,    g_yp);
    cudaGetSymbolAddress((void**)&gop,    g_op);
    cudaGetSymbolAddress((void**)&ghp,    g_hp);
    cudaGetSymbolAddress((void**)&gwqkvp, g_wqkvp);
    cudaGetSymbolAddress((void**)&gwop,   g_wop);
    cudaGetSymbolAddress((void**)&gw1p,   g_w1p);
    cudaGetSymbolAddress((void**)&gw2p,   g_w2p);

    cudaMemcpyAsync(gx, x, (size_t)BN_ROWS * DIMD * sizeof(float),
                    cudaMemcpyDeviceToDevice, 0);

    // Batched weight transpose -> bf16 (grid.z = DEPTH)
    wconv_kernel<<<dim3(384/32, 384/32, DEPTH), 256>>>(
        wq,  gwqkvp, 384, 384,  0,   (size_t)DIMD*INNERD,   (size_t)1152*DIMD);
    wconv_kernel<<<dim3(768/32, 384/32, DEPTH), 256>>>(
        wkv, gwqkvp, 384, 768,  384, (size_t)DIMD*2*INNERD, (size_t)1152*DIMD);
    wconv_kernel<<<dim3(384/32, 384/32, DEPTH), 256>>>(
        wo,  gwop,   384, 384,  0,   (size_t)INNERD*DIMD,   (size_t)384*DIMD);
    wconv_kernel<<<dim3(1536/32, 384/32, DEPTH), 256>>>(
        w1,  gw1p,   384, 1536, 0,   (size_t)DIMD*MLPD,     (size_t)1536*DIMD);
    wconv_kernel<<<dim3(384/32, 1536/32, DEPTH), 256>>>(
        w2,  gw2p,   1536, 384, 0,   (size_t)MLPD*DIMD,     (size_t)384*MLPD);

    for (int L = 0; L < DEPTH; L++) {
        const __nv_bfloat16* L_wqkvp = gwqkvp + (size_t)L*1152*DIMD;
        const __nv_bfloat16* L_wop   = gwop   + (size_t)L*384*DIMD;
        const __nv_bfloat16* L_w1p   = gw1p   + (size_t)L*1536*DIMD;
        const __nv_bfloat16* L_w2p   = gw2p   + (size_t)L*384*MLPD;

        // Attention
        ln_bf16_kernel<<<BN_ROWS, 128>>>(gx, ln1g + L*DIMD, ln1b + L*DIMD, gyp);
        tc_gemm<3><<<dim3(1152/128, BN_ROWS/128), 256, GEMM_DSMEM>>>(
            gyp, L_wqkvp, DIMD, 1152, DIMD/32, nullptr, gqkv, 0,
            nullptr, nullptr, nullptr);
        dots_mma<<<dim3(2, 2, BB*HH), 256>>>(gqkv, scl + L*HH, gdots);
        softmax_mix_kernel<<<BB*NN, 256>>>(gdots, mp + L*HH*HH, mq + L*HH*HH, gattn);
        attnv_mma<<<dim3(2, BB*HH), 256>>>(gattn, gqkv, gop);
        tc_gemm<2><<<dim3(384/128, BN_ROWS/128), 256, GEMM_DSMEM>>>(
            gop, L_wop, DIMD, 384, DIMD/32, gx, nullptr, 0,
            bo + L*DIMD, ls1 + L*DIMD, gx);

        // FFN
        ln_bf16_kernel<<<BN_ROWS, 128>>>(gx, ln2g + L*DIMD, ln2b + L*DIMD, gyp);
        tc_gemm<1><<<dim3(1536/128, BN_ROWS/128), 256, GEMM_DSMEM>>>(
            gyp, L_w1p, DIMD, 1536, DIMD/32, nullptr, ghp, MLPD,
            b1 + L*MLPD, nullptr, nullptr);
        tc_gemm<2><<<dim3(384/128, BN_ROWS/128), 256, GEMM_DSMEM>>>(
            ghp, L_w2p, MLPD, 384, MLPD/32, gx, nullptr, 0,
            b2 + L*DIMD, ls2 + L*DIMD, gx);
    }

    cudaMemcpyAsync(d_out, gx, (size_t)BN_ROWS * DIMD * sizeof(float),
                    cudaMemcpyDeviceToDevice, 0);
}

// round 14
// speedup vs baseline: 3.5125x; 1.0051x over previous
#include <cuda_runtime.h>
#include <cuda_bf16.h>
#include <math.h>
#include <stdint.h>

// Problem dims
#define BB   32
#define NN   256
#define DIMD 384
#define HH   6
#define DHD  64
#define MLPD 1536
#define DEPTH 12
#define INNERD 384
#define BN_ROWS (BB*NN)          // 8192
#define K3Q (3*DIMD)             // 1152 (qkv output cols)

// ---------------------------------------------------------------------------
// Device scratch
// ---------------------------------------------------------------------------
__device__ __align__(128) float g_x   [BN_ROWS*DIMD];
__device__ __align__(128) float g_dots[(size_t)BB*HH*NN*NN];
__device__ __align__(128) __nv_bfloat16 g_qkv [(size_t)BN_ROWS*K3Q];
__device__ __align__(128) __nv_bfloat16 g_attn[(size_t)BB*HH*NN*NN];
__device__ __align__(128) __nv_bfloat16 g_yp[(size_t)BN_ROWS*DIMD];
__device__ __align__(128) __nv_bfloat16 g_op[(size_t)BN_ROWS*DIMD];
__device__ __align__(128) __nv_bfloat16 g_hp[(size_t)BN_ROWS*MLPD];
__device__ __align__(128) __nv_bfloat16 g_wqkvp[(size_t)DEPTH*1152*DIMD];
__device__ __align__(128) __nv_bfloat16 g_wop  [(size_t)DEPTH*384 *DIMD];
__device__ __align__(128) __nv_bfloat16 g_w1p  [(size_t)DEPTH*1536*DIMD];
__device__ __align__(128) __nv_bfloat16 g_w2p  [(size_t)DEPTH*384 *MLPD];

// ---------------------------------------------------------------------------
// Helpers
// ---------------------------------------------------------------------------
__device__ __forceinline__ uint32_t cvta_s(const void* p) {
    uint32_t a;
    asm("{ .reg .u64 t; cvta.to.shared.u64 t, %1; cvt.u32.u64 %0, t; }"
        : "=r"(a) : "l"(p));
    return a;
}
#define CP_ASYNC16(dst, src) \
    asm volatile("cp.async.cg.shared.global [%0], [%1], 16;" :: "r"(dst), "l"(src))
#define CP_COMMIT()  asm volatile("cp.async.commit_group;")
#define CP_WAIT1()   asm volatile("cp.async.wait_group 1;" ::: "memory")

__device__ __forceinline__ void mma16816(float* d, const uint32_t* a, const uint32_t* b) {
    asm volatile(
        "mma.sync.aligned.m16n8k16.row.col.f32.bf16.bf16.f32 "
        "{%0,%1,%2,%3}, {%4,%5,%6,%7}, {%8,%9}, {%0,%1,%2,%3};\n"
        : "+f"(d[0]), "+f"(d[1]), "+f"(d[2]), "+f"(d[3])
        : "r"(a[0]), "r"(a[1]), "r"(a[2]), "r"(a[3]), "r"(b[0]), "r"(b[1]));
}

// ---------------------------------------------------------------------------
// Batched weight transpose to bf16: per layer z, W[K,N] fp32 -> out[n][k] bf16
// ---------------------------------------------------------------------------
__global__ __launch_bounds__(256) void wconv_kernel(
    const float* __restrict__ W, __nv_bfloat16* __restrict__ out,
    int K, int N, int rowOff, size_t wStride, size_t oStride)
{
    const float* Wl = W + (size_t)blockIdx.z * wStride;
    __nv_bfloat16* ol = out + (size_t)blockIdx.z * oStride;

    __shared__ float tile[32][33];
    int k0 = blockIdx.y * 32, n0 = blockIdx.x * 32;
    int tx = threadIdx.x & 31, ty = threadIdx.x >> 5;
    #pragma unroll
    for (int i = 0; i < 4; i++) {
        int r = ty + i * 8;
        tile[r][tx] = Wl[(size_t)(k0 + r) * N + n0 + tx];
    }
    __syncthreads();
    #pragma unroll
    for (int i = 0; i < 4; i++) {
        int r = ty + i * 8;
        ol[(size_t)(rowOff + n0 + r) * K + k0 + tx] = __float2bfloat16(tile[tx][r]);
    }
}

// ---------------------------------------------------------------------------
// LayerNorm -> plain bf16 output
// ---------------------------------------------------------------------------
__global__ __launch_bounds__(128) void ln_bf16_kernel(
    const float* __restrict__ x, const float* __restrict__ g,
    const float* __restrict__ b, __nv_bfloat16* __restrict__ yp)
{
    int row = blockIdx.x;
    int t = threadIdx.x;
    const float* xr = x + (size_t)row * DIMD;
    float v0 = xr[t], v1 = xr[t + 128], v2 = xr[t + 256];

    __shared__ float scratch[4];
    float s = v0 + v1 + v2;
    #pragma unroll
    for (int o = 16; o; o >>= 1) s += __shfl_xor_sync(0xffffffffu, s, o);
    if ((t & 31) == 0) scratch[t >> 5] = s;
    __syncthreads();
    s = scratch[0] + scratch[1] + scratch[2] + scratch[3];
    float mean = s * (1.0f / DIMD);

    float d0 = v0 - mean, d1 = v1 - mean, d2 = v2 - mean;
    float q = d0 * d0 + d1 * d1 + d2 * d2;
    __syncthreads();
    #pragma unroll
    for (int o = 16; o; o >>= 1) q += __shfl_xor_sync(0xffffffffu, q, o);
    if ((t & 31) == 0) scratch[t >> 5] = q;
    __syncthreads();
    q = scratch[0] + scratch[1] + scratch[2] + scratch[3];
    float rstd = rsqrtf(q * (1.0f / DIMD) + 1e-5f);

    __nv_bfloat16* yr = yp + (size_t)row * DIMD;
    yr[t]       = __float2bfloat16(d0 * rstd * g[t]       + b[t]);
    yr[t + 128] = __float2bfloat16(d1 * rstd * g[t + 128] + b[t + 128]);
    yr[t + 256] = __float2bfloat16(d2 * rstd * g[t + 256] + b[t + 256]);
}

// ---------------------------------------------------------------------------
// HMMA bf16 GEMM, 3-stage cp.async pipeline (60KB dsmem), 2 CTAs/SM.
// 128x128x32 tile, 8 warps (64x32 each), scalar-LDS fragment loads.
// EPI 1: gelu(c+bias) -> bf16 (stride KsegOut).
// EPI 2: (c+bias)*ls + res -> fp32.
// EPI 3: plain bf16 out (stride N).
// ---------------------------------------------------------------------------
#define GPITCH 40
#define STAGE_H (128 * GPITCH)
#define NSTAGE 3
#define GEMM_DSMEM (2 * NSTAGE * STAGE_H * 2)   // 61440 B

template<int EPI>
__global__ __launch_bounds__(256, 2) void tc_gemm(
    const __nv_bfloat16* __restrict__ A, const __nv_bfloat16* __restrict__ W,
    int K3, int N, int nchunks,
    float* __restrict__ Cf, __nv_bfloat16* __restrict__ Cs, int KsegOut,
    const float* __restrict__ bias, const float* __restrict__ ls,
    const float* __restrict__ res)
{
    extern __shared__ __nv_bfloat16 dsm[];
    __nv_bfloat16* Asm = dsm;
    __nv_bfloat16* Bsm = dsm + NSTAGE * STAGE_H;

    int tid = threadIdx.x, lane = tid & 31, wid = tid >> 5;
    __builtin_assume(tid < 256);
    int wm = wid & 1, wn = wid >> 1;
    int m0 = blockIdx.y * 128, n0 = blockIdx.x * 128;

    float acc[4][4][4] = {};

    auto load_chunk = [&](int c, int buf) {
        int k0 = c * 32;
        #pragma unroll
        for (int rep = 0; rep < 2; rep++) {
            int u = tid + rep * 256;
            int row = u >> 2, q = u & 3;
            uint32_t da = cvta_s(&Asm[buf * STAGE_H + row * GPITCH + q * 8]);
            uint32_t db = cvta_s(&Bsm[buf * STAGE_H + row * GPITCH + q * 8]);
            CP_ASYNC16(da, A + (size_t)(m0 + row) * K3 + k0 + q * 8);
            CP_ASYNC16(db, W + (size_t)(n0 + row) * K3 + k0 + q * 8);
        }
        CP_COMMIT();
    };

    load_chunk(0, 0);
    load_chunk(1, 1);

    int cbuf = 0, lbuf = 2;
    for (int c = 0; c < nchunks; c++) {
        CP_WAIT1();
        __syncthreads();
        if (c + 2 < nchunks) load_chunk(c + 2, lbuf);
        else                 CP_COMMIT();

        const __nv_bfloat16* Ab = Asm + cbuf * STAGE_H;
        const __nv_bfloat16* Bb = Bsm + cbuf * STAGE_H;
        #pragma unroll
        for (int kk = 0; kk < 32; kk += 16) {
            int kc = kk + (lane & 3) * 2;
            uint32_t af[4][4], bf[4][2];
            #pragma unroll
            for (int mi = 0; mi < 4; mi++) {
                int r = wm * 64 + mi * 16 + (lane >> 2);
                af[mi][0] = *(const uint32_t*)&Ab[r * GPITCH + kc];
                af[mi][1] = *(const uint32_t*)&Ab[(r + 8) * GPITCH + kc];
                af[mi][2] = *(const uint32_t*)&Ab[r * GPITCH + kc + 8];
                af[mi][3] = *(const uint32_t*)&Ab[(r + 8) * GPITCH + kc + 8];
            }
            #pragma unroll
            for (int ni = 0; ni < 4; ni++) {
                int n = wn * 32 + ni * 8 + (lane >> 2);
                bf[ni][0] = *(const uint32_t*)&Bb[n * GPITCH + kc];
                bf[ni][1] = *(const uint32_t*)&Bb[n * GPITCH + kc + 8];
            }
            #pragma unroll
            for (int mi = 0; mi < 4; mi++)
                #pragma unroll
                for (int ni = 0; ni < 4; ni++)
                    mma16816(acc[mi][ni], af[mi], bf[ni]);
        }
        cbuf = (cbuf == 2) ? 0 : cbuf + 1;
        lbuf = (lbuf == 2) ? 0 : lbuf + 1;
    }

    #pragma unroll
    for (int mi = 0; mi < 4; mi++) {
        #pragma unroll
        for (int ni = 0; ni < 4; ni++) {
            int col = n0 + wn * 32 + ni * 8 + (lane & 3) * 2;
            #pragma unroll
            for (int hh = 0; hh < 2; hh++) {
                int m = m0 + wm * 64 + mi * 16 + (lane >> 2) + hh * 8;
                float v0 = acc[mi][ni][hh * 2 + 0];
                float v1 = acc[mi][ni][hh * 2 + 1];
                if (EPI == 1) {
                    #pragma unroll
                    for (int e = 0; e < 2; e++) {
                        float v = (e ? v1 : v0) + bias[col + e];
                        v = 0.5f * v * (1.0f + erff(v * 0.70710678118654752f));
                        Cs[(size_t)m * KsegOut + col + e] = __float2bfloat16(v);
                    }
                } else if (EPI == 2) {
                    size_t i0 = (size_t)m * N + col;
                    Cf[i0]     = (v0 + bias[col])     * ls[col]     + res[i0];
                    Cf[i0 + 1] = (v1 + bias[col + 1]) * ls[col + 1] + res[i0 + 1];
                } else {   // EPI == 3: plain bf16
                    Cs[(size_t)m * N + col]     = __float2bfloat16(v0);
                    Cs[(size_t)m * N + col + 1] = __float2bfloat16(v1);
                }
            }
        }
    }
}

// ---------------------------------------------------------------------------
// dots via HMMA: per z=(b,h) tile 128x128, K=64. q,k bf16 from fused qkv.
// grid (2, 2, 192). dots written fp32 (scaled).
// ---------------------------------------------------------------------------
#define DP 72    // halves pitch

__global__ __launch_bounds__(256) void dots_mma(
    const __nv_bfloat16* __restrict__ qkv, const float* __restrict__ scale,
    float* __restrict__ dots)
{
    __shared__ __nv_bfloat16 Qs[128 * DP];
    __shared__ __nv_bfloat16 Ks[128 * DP];

    int z = blockIdx.z;
    int b = z / HH, h = z % HH;
    int i0 = blockIdx.y * 128, j0 = blockIdx.x * 128;

    int tid = threadIdx.x, lane = tid & 31, wid = tid >> 5;
    __builtin_assume(tid < 256);
    int wm = wid & 1, wn = wid >> 1;

    #pragma unroll
    for (int it = 0; it < 4; it++) {
        int u = tid + it * 256;
        int r = u >> 3, q = u & 7;
        *(uint4*)&Qs[r * DP + q * 8] =
            *(const uint4*)&qkv[(size_t)(b * NN + i0 + r) * K3Q + h * DHD + q * 8];
        *(uint4*)&Ks[r * DP + q * 8] =
            *(const uint4*)&qkv[(size_t)(b * NN + j0 + r) * K3Q + 384 + h * DHD + q * 8];
    }
    __syncthreads();

    float acc[4][4][4] = {};
    #pragma unroll
    for (int kk = 0; kk < 64; kk += 16) {
        int kc = kk + (lane & 3) * 2;
        uint32_t af[4][4], bf[4][2];
        #pragma unroll
        for (int mi = 0; mi < 4; mi++) {
            int r = wm * 64 + mi * 16 + (lane >> 2);
            af[mi][0] = *(const uint32_t*)&Qs[r * DP + kc];
            af[mi][1] = *(const uint32_t*)&Qs[(r + 8) * DP + kc];
            af[mi][2] = *(const uint32_t*)&Qs[r * DP + kc + 8];
            af[mi][3] = *(const uint32_t*)&Qs[(r + 8) * DP + kc + 8];
        }
        #pragma unroll
        for (int ni = 0; ni < 4; ni++) {
            int n = wn * 32 + ni * 8 + (lane >> 2);
            bf[ni][0] = *(const uint32_t*)&Ks[n * DP + kc];
            bf[ni][1] = *(const uint32_t*)&Ks[n * DP + kc + 8];
        }
        #pragma unroll
        for (int mi = 0; mi < 4; mi++)
            #pragma unroll
            for (int ni = 0; ni < 4; ni++)
                mma16816(acc[mi][ni], af[mi], bf[ni]);
    }

    float sc = scale[h];
    float* C = dots + (size_t)z * NN * NN;
    #pragma unroll
    for (int mi = 0; mi < 4; mi++)
        #pragma unroll
        for (int ni = 0; ni < 4; ni++) {
            int col = j0 + wn * 32 + ni * 8 + (lane & 3) * 2;
            #pragma unroll
            for (int hh = 0; hh < 2; hh++) {
                int m = i0 + wm * 64 + mi * 16 + (lane >> 2) + hh * 8;
                C[(size_t)m * NN + col]     = acc[mi][ni][hh * 2 + 0] * sc;
                C[(size_t)m * NN + col + 1] = acc[mi][ni][hh * 2 + 1] * sc;
            }
        }
}

// ---------------------------------------------------------------------------
// Fused pre-mix -> mask -> softmax -> post-mix; writes attn as bf16
// ---------------------------------------------------------------------------
__global__ __launch_bounds__(256) void softmax_mix_kernel(
    const float* __restrict__ dots, const float* __restrict__ mp,
    const float* __restrict__ mq, __nv_bfloat16* __restrict__ attn)
{
    int b = blockIdx.x >> 8;
    int i = blockIdx.x & 255;
    int j = threadIdx.x;
    int lane = j & 31, wrp = j >> 5;

    __shared__ float smp[36], smq[36];
    __shared__ float red[8][6];
    if (j < 36) { smp[j] = mp[j]; smq[j] = mq[j]; }

    float raw[HH];
    #pragma unroll
    for (int h = 0; h < HH; h++)
        raw[h] = dots[(((size_t)(b * HH + h)) * NN + i) * NN + j];
    __syncthreads();

    float pm[HH];
    #pragma unroll
    for (int g = 0; g < HH; g++) {
        float s = 0.0f;
        #pragma unroll
        for (int h = 0; h < HH; h++) s = fmaf(raw[h], smp[h * HH + g], s);
        pm[g] = s;
    }
    if (j == i) {
        #pragma unroll
        for (int g = 0; g < HH; g++) pm[g] = -INFINITY;
    }

    float mx[HH];
    #pragma unroll
    for (int g = 0; g < HH; g++) mx[g] = pm[g];
    #pragma unroll
    for (int o = 16; o; o >>= 1)
        #pragma unroll
        for (int g = 0; g < HH; g++)
            mx[g] = fmaxf(mx[g], __shfl_xor_sync(0xffffffffu, mx[g], o));
    if (lane == 0)
        #pragma unroll
        for (int g = 0; g < HH; g++) red[wrp][g] = mx[g];
    __syncthreads();
    #pragma unroll
    for (int g = 0; g < HH; g++) {
        float m = red[0][g];
        #pragma unroll
        for (int w = 1; w < 8; w++) m = fmaxf(m, red[w][g]);
        mx[g] = m;
    }
    __syncthreads();

    float ex[HH], sm[HH];
    #pragma unroll
    for (int g = 0; g < HH; g++) { ex[g] = expf(pm[g] - mx[g]); sm[g] = ex[g]; }
    #pragma unroll
    for (int o = 16; o; o >>= 1)
        #pragma unroll
        for (int g = 0; g < HH; g++)
            sm[g] += __shfl_xor_sync(0xffffffffu, sm[g], o);
    if (lane == 0)
        #pragma unroll
        for (int g = 0; g < HH; g++) red[wrp][g] = sm[g];
    __syncthreads();
    float a[HH];
    #pragma unroll
    for (int g = 0; g < HH; g++) {
        float s = red[0][g];
        #pragma unroll
        for (int w = 1; w < 8; w++) s += red[w][g];
        a[g] = ex[g] / s;
    }

    #pragma unroll
    for (int g = 0; g < HH; g++) {
        float s = 0.0f;
        #pragma unroll
        for (int h = 0; h < HH; h++) s = fmaf(a[h], smq[h * HH + g], s);
        attn[(((size_t)(b * HH + g)) * NN + i) * NN + j] = __float2bfloat16(s);
    }
}

// ---------------------------------------------------------------------------
// attn*V via HMMA: per z=(b,h): O[256,64] = attn[z](bf16) x v[z](bf16), K=256.
// Tile 128x64, 8 warps (4M x 2N, 32x32 each). V transposed in smem.
// grid (2, 192). Writes g_op bf16.
// ---------------------------------------------------------------------------
__global__ __launch_bounds__(256) void attnv_mma(
    const __nv_bfloat16* __restrict__ attn, const __nv_bfloat16* __restrict__ qkv,
    __nv_bfloat16* __restrict__ op)
{
    __shared__ __nv_bfloat16 As[128 * DP];     // attn tile
    __shared__ __nv_bfloat16 Vs16[64][DP];     // V staging [j][d]
    __shared__ __nv_bfloat16 Vst[64 * DP];     // V^T [d][j]

    int z = blockIdx.y;
    int b = z / HH, h = z % HH;
    int i0 = blockIdx.x * 128;

    int tid = threadIdx.x, lane = tid & 31, wid = tid >> 5;
    __builtin_assume(tid < 256);
    int wm = wid & 3, wn = wid >> 2;

    const __nv_bfloat16* abase = attn + (size_t)z * NN * NN;
    const __nv_bfloat16* vbase = qkv + 768 + h * DHD;

    float acc[2][4][4] = {};

    for (int c = 0; c < 4; c++) {
        int j0 = c * 64;
        #pragma unroll
        for (int it = 0; it < 4; it++) {
            int u = tid + it * 256;
            int r = u >> 3, q = u & 7;
            *(uint4*)&As[r * DP + q * 8] =
                *(const uint4*)&abase[(size_t)(i0 + r) * NN + j0 + q * 8];
        }
        #pragma unroll
        for (int it = 0; it < 2; it++) {
            int u = tid + it * 256;
            int r = u >> 3, q = u & 7;
            *(uint4*)&Vs16[r][q * 8] =
                *(const uint4*)&vbase[(size_t)(b * NN + j0 + r) * K3Q + q * 8];
        }
        __syncthreads();
        #pragma unroll
        for (int it = 0; it < 8; it++) {
            int u = tid + it * 256;
            int d = u & 63, jp = u >> 6;
            __nv_bfloat162 p;
            p.x = Vs16[2 * jp][d];
            p.y = Vs16[2 * jp + 1][d];
            *(__nv_bfloat162*)&Vst[d * DP + jp * 2] = p;
        }
        __syncthreads();

        #pragma unroll
        for (int kk = 0; kk < 64; kk += 16) {
            int kc = kk + (lane & 3) * 2;
            uint32_t af[2][4], bf[4][2];
            #pragma unroll
            for (int mi = 0; mi < 2; mi++) {
                int r = wm * 32 + mi * 16 + (lane >> 2);
                af[mi][0] = *(const uint32_t*)&As[r * DP + kc];
                af[mi][1] = *(const uint32_t*)&As[(r + 8) * DP + kc];
                af[mi][2] = *(const uint32_t*)&As[r * DP + kc + 8];
                af[mi][3] = *(const uint32_t*)&As[(r + 8) * DP + kc + 8];
            }
            #pragma unroll
            for (int ni = 0; ni < 4; ni++) {
                int n = wn * 32 + ni * 8 + (lane >> 2);
                bf[ni][0] = *(const uint32_t*)&Vst[n * DP + kc];
                bf[ni][1] = *(const uint32_t*)&Vst[n * DP + kc + 8];
            }
            #pragma unroll
            for (int mi = 0; mi < 2; mi++)
                #pragma unroll
                for (int ni = 0; ni < 4; ni++)
                    mma16816(acc[mi][ni], af[mi], bf[ni]);
        }
        __syncthreads();
    }

    #pragma unroll
    for (int mi = 0; mi < 2; mi++)
        #pragma unroll
        for (int ni = 0; ni < 4; ni++) {
            int d0 = wn * 32 + ni * 8 + (lane & 3) * 2;
            #pragma unroll
            for (int hh = 0; hh < 2; hh++) {
                int i = i0 + wm * 32 + mi * 16 + (lane >> 2) + hh * 8;
                size_t row = (size_t)b * NN + i;
                op[row * DIMD + h * DHD + d0]     =
                    __float2bfloat16(acc[mi][ni][hh * 2 + 0]);
                op[row * DIMD + h * DHD + d0 + 1] =
                    __float2bfloat16(acc[mi][ni][hh * 2 + 1]);
            }
        }
}

// ---------------------------------------------------------------------------
// Launch
// ---------------------------------------------------------------------------
extern "C" void kernel_launch(void* const* d_in, const int* in_sizes, int n_in,
                              void* d_out, int out_size)
{
    const float* x    = (const float*)d_in[0];
    const float* ln1g = (const float*)d_in[1];
    const float* ln1b = (const float*)d_in[2];
    const float* wq   = (const float*)d_in[3];
    const float* wkv  = (const float*)d_in[4];
    const float* scl  = (const float*)d_in[5];
    const float* mp   = (const float*)d_in[6];
    const float* mq   = (const float*)d_in[7];
    const float* wo   = (const float*)d_in[8];
    const float* bo   = (const float*)d_in[9];
    const float* ls1  = (const float*)d_in[10];
    const float* ln2g = (const float*)d_in[11];
    const float* ln2b = (const float*)d_in[12];
    const float* w1   = (const float*)d_in[13];
    const float* b1   = (const float*)d_in[14];
    const float* w2   = (const float*)d_in[15];
    const float* b2   = (const float*)d_in[16];
    const float* ls2  = (const float*)d_in[17];

    cudaFuncSetAttribute(tc_gemm<1>, cudaFuncAttributeMaxDynamicSharedMemorySize, GEMM_DSMEM);
    cudaFuncSetAttribute(tc_gemm<2>, cudaFuncAttributeMaxDynamicSharedMemorySize, GEMM_DSMEM);
    cudaFuncSetAttribute(tc_gemm<3>, cudaFuncAttributeMaxDynamicSharedMemorySize, GEMM_DSMEM);

    float *gx, *gdots;
    __nv_bfloat16 *gqkv, *gattn, *gyp, *gop, *ghp, *gwqkvp, *gwop, *gw1p, *gw2p;
    cudaGetSymbolAddress((void**)&gx,     g_x);
    cudaGetSymbolAddress((void**)&gqkv,   g_qkv);
    cudaGetSymbolAddress((void**)&gdots,  g_dots);
    cudaGetSymbolAddress((void**)&gattn,  g_attn);
    cudaGetSymbolAddress((void**)&gyp,    g_yp);
    cudaGetSymbolAddress((void**)&gop,    g_op);
    cudaGetSymbolAddress((void**)&ghp,    g_hp);
    cudaGetSymbolAddress((void**)&gwqkvp, g_wqkvp);
    cudaGetSymbolAddress((void**)&gwop,   g_wop);
    cudaGetSymbolAddress((void**)&gw1p,   g_w1p);
    cudaGetSymbolAddress((void**)&gw2p,   g_w2p);

    cudaMemcpyAsync(gx, x, (size_t)BN_ROWS * DIMD * sizeof(float),
                    cudaMemcpyDeviceToDevice, 0);

    // Batched weight transpose -> bf16 (grid.z = DEPTH)
    wconv_kernel<<<dim3(384/32, 384/32, DEPTH), 256>>>(
        wq,  gwqkvp, 384, 384,  0,   (size_t)DIMD*INNERD,   (size_t)1152*DIMD);
    wconv_kernel<<<dim3(768/32, 384/32, DEPTH), 256>>>(
        wkv, gwqkvp, 384, 768,  384, (size_t)DIMD*2*INNERD, (size_t)1152*DIMD);
    wconv_kernel<<<dim3(384/32, 384/32, DEPTH), 256>>>(
        wo,  gwop,   384, 384,  0,   (size_t)INNERD*DIMD,   (size_t)384*DIMD);
    wconv_kernel<<<dim3(1536/32, 384/32, DEPTH), 256>>>(
        w1,  gw1p,   384, 1536, 0,   (size_t)DIMD*MLPD,     (size_t)1536*DIMD);
    wconv_kernel<<<dim3(384/32, 1536/32, DEPTH), 256>>>(
        w2,  gw2p,   1536, 384, 0,   (size_t)MLPD*DIMD,     (size_t)384*MLPD);

    for (int L = 0; L < DEPTH; L++) {
        const __nv_bfloat16* L_wqkvp = gwqkvp + (size_t)L*1152*DIMD;
        const __nv_bfloat16* L_wop   = gwop   + (size_t)L*384*DIMD;
        const __nv_bfloat16* L_w1p   = gw1p   + (size_t)L*1536*DIMD;
        const __nv_bfloat16* L_w2p   = gw2p   + (size_t)L*384*MLPD;

        // Attention
        ln_bf16_kernel<<<BN_ROWS, 128>>>(gx, ln1g + L*DIMD, ln1b + L*DIMD, gyp);
        tc_gemm<3><<<dim3(1152/128, BN_ROWS/128), 256, GEMM_DSMEM>>>(
            gyp, L_wqkvp, DIMD, 1152, DIMD/32, nullptr, gqkv, 0,
            nullptr, nullptr, nullptr);
        dots_mma<<<dim3(2, 2, BB*HH), 256>>>(gqkv, scl + L*HH, gdots);
        softmax_mix_kernel<<<BB*NN, 256>>>(gdots, mp + L*HH*HH, mq + L*HH*HH, gattn);
        attnv_mma<<<dim3(2, BB*HH), 256>>>(gattn, gqkv, gop);
        tc_gemm<2><<<dim3(384/128, BN_ROWS/128), 256, GEMM_DSMEM>>>(
            gop, L_wop, DIMD, 384, DIMD/32, gx, nullptr, 0,
            bo + L*DIMD, ls1 + L*DIMD, gx);

        // FFN
        ln_bf16_kernel<<<BN_ROWS, 128>>>(gx, ln2g + L*DIMD, ln2b + L*DIMD, gyp);
        tc_gemm<1><<<dim3(1536/128, BN_ROWS/128), 256, GEMM_DSMEM>>>(
            gyp, L_w1p, DIMD, 1536, DIMD/32, nullptr, ghp, MLPD,
            b1 + L*MLPD, nullptr, nullptr);
        tc_gemm<2><<<dim3(384/128, BN_ROWS/128), 256, GEMM_DSMEM>>>(
            ghp, L_w2p, MLPD, 384, MLPD/32, gx, nullptr, 0,
            b2 + L*DIMD, ls2 + L*DIMD, gx);
    }

    cudaMemcpyAsync(d_out, gx, (size_t)BN_ROWS * DIMD * sizeof(float),
                    cudaMemcpyDeviceToDevice, 0);
}

// round 16
// speedup vs baseline: 3.5978x; 1.0243x over previous
#include <cuda_runtime.h>
#include <cuda_bf16.h>
#include <math.h>
#include <stdint.h>

// Problem dims
#define BB   32
#define NN   256
#define DIMD 384
#define HH   6
#define DHD  64
#define MLPD 1536
#define DEPTH 12
#define INNERD 384
#define BN_ROWS (BB*NN)          // 8192
#define K3Q (3*DIMD)             // 1152 (qkv output cols)

// ---------------------------------------------------------------------------
// Device scratch
// ---------------------------------------------------------------------------
__device__ __align__(128) float g_x   [BN_ROWS*DIMD];
__device__ __align__(128) __nv_bfloat16 g_dots[(size_t)BB*HH*NN*NN];
__device__ __align__(128) __nv_bfloat16 g_qkv [(size_t)BN_ROWS*K3Q];
__device__ __align__(128) __nv_bfloat16 g_attn[(size_t)BB*HH*NN*NN];
__device__ __align__(128) __nv_bfloat16 g_yp[(size_t)BN_ROWS*DIMD];
__device__ __align__(128) __nv_bfloat16 g_op[(size_t)BN_ROWS*DIMD];
__device__ __align__(128) __nv_bfloat16 g_hp[(size_t)BN_ROWS*MLPD];
__device__ __align__(128) __nv_bfloat16 g_wqkvp[(size_t)DEPTH*1152*DIMD];
__device__ __align__(128) __nv_bfloat16 g_wop  [(size_t)DEPTH*384 *DIMD];
__device__ __align__(128) __nv_bfloat16 g_w1p  [(size_t)DEPTH*1536*DIMD];
__device__ __align__(128) __nv_bfloat16 g_w2p  [(size_t)DEPTH*384 *MLPD];

// ---------------------------------------------------------------------------
// Helpers
// ---------------------------------------------------------------------------
__device__ __forceinline__ uint32_t cvta_s(const void* p) {
    uint32_t a;
    asm("{ .reg .u64 t; cvta.to.shared.u64 t, %1; cvt.u32.u64 %0, t; }"
        : "=r"(a) : "l"(p));
    return a;
}
#define CP_ASYNC16(dst, src) \
    asm volatile("cp.async.cg.shared.global [%0], [%1], 16;" :: "r"(dst), "l"(src))
#define CP_COMMIT()  asm volatile("cp.async.commit_group;")
#define CP_WAIT1()   asm volatile("cp.async.wait_group 1;" ::: "memory")

__device__ __forceinline__ void mma16816(float* d, const uint32_t* a, const uint32_t* b) {
    asm volatile(
        "mma.sync.aligned.m16n8k16.row.col.f32.bf16.bf16.f32 "
        "{%0,%1,%2,%3}, {%4,%5,%6,%7}, {%8,%9}, {%0,%1,%2,%3};\n"
        : "+f"(d[0]), "+f"(d[1]), "+f"(d[2]), "+f"(d[3])
        : "r"(a[0]), "r"(a[1]), "r"(a[2]), "r"(a[3]), "r"(b[0]), "r"(b[1]));
}

// ---------------------------------------------------------------------------
// Batched weight transpose to bf16: per layer z, W[K,N] fp32 -> out[n][k] bf16
// ---------------------------------------------------------------------------
__global__ __launch_bounds__(256) void wconv_kernel(
    const float* __restrict__ W, __nv_bfloat16* __restrict__ out,
    int K, int N, int rowOff, size_t wStride, size_t oStride)
{
    const float* Wl = W + (size_t)blockIdx.z * wStride;
    __nv_bfloat16* ol = out + (size_t)blockIdx.z * oStride;

    __shared__ float tile[32][33];
    int k0 = blockIdx.y * 32, n0 = blockIdx.x * 32;
    int tx = threadIdx.x & 31, ty = threadIdx.x >> 5;
    #pragma unroll
    for (int i = 0; i < 4; i++) {
        int r = ty + i * 8;
        tile[r][tx] = Wl[(size_t)(k0 + r) * N + n0 + tx];
    }
    __syncthreads();
    #pragma unroll
    for (int i = 0; i < 4; i++) {
        int r = ty + i * 8;
        ol[(size_t)(rowOff + n0 + r) * K + k0 + tx] = __float2bfloat16(tile[tx][r]);
    }
}

// ---------------------------------------------------------------------------
// LayerNorm -> plain bf16 output
// ---------------------------------------------------------------------------
__global__ __launch_bounds__(128) void ln_bf16_kernel(
    const float* __restrict__ x, const float* __restrict__ g,
    const float* __restrict__ b, __nv_bfloat16* __restrict__ yp)
{
    int row = blockIdx.x;
    int t = threadIdx.x;
    const float* xr = x + (size_t)row * DIMD;
    float v0 = xr[t], v1 = xr[t + 128], v2 = xr[t + 256];

    __shared__ float scratch[4];
    float s = v0 + v1 + v2;
    #pragma unroll
    for (int o = 16; o; o >>= 1) s += __shfl_xor_sync(0xffffffffu, s, o);
    if ((t & 31) == 0) scratch[t >> 5] = s;
    __syncthreads();
    s = scratch[0] + scratch[1] + scratch[2] + scratch[3];
    float mean = s * (1.0f / DIMD);

    float d0 = v0 - mean, d1 = v1 - mean, d2 = v2 - mean;
    float q = d0 * d0 + d1 * d1 + d2 * d2;
    __syncthreads();
    #pragma unroll
    for (int o = 16; o; o >>= 1) q += __shfl_xor_sync(0xffffffffu, q, o);
    if ((t & 31) == 0) scratch[t >> 5] = q;
    __syncthreads();
    q = scratch[0] + scratch[1] + scratch[2] + scratch[3];
    float rstd = rsqrtf(q * (1.0f / DIMD) + 1e-5f);

    __nv_bfloat16* yr = yp + (size_t)row * DIMD;
    yr[t]       = __float2bfloat16(d0 * rstd * g[t]       + b[t]);
    yr[t + 128] = __float2bfloat16(d1 * rstd * g[t + 128] + b[t + 128]);
    yr[t + 256] = __float2bfloat16(d2 * rstd * g[t + 256] + b[t + 256]);
}

// ---------------------------------------------------------------------------
// HMMA bf16 GEMM, 3-stage cp.async pipeline (60KB dsmem), 2 CTAs/SM.
// 128x128x32 tile, 8 warps (64x32 each), scalar-LDS fragment loads.
// EPI 1: gelu(c+bias) -> bf16 (stride KsegOut).
// EPI 2: (c+bias)*ls + res -> fp32.
// EPI 3: plain bf16 out (stride N).
// ---------------------------------------------------------------------------
#define GPITCH 40
#define STAGE_H (128 * GPITCH)
#define NSTAGE 3
#define GEMM_DSMEM (2 * NSTAGE * STAGE_H * 2)   // 61440 B

template<int EPI>
__global__ __launch_bounds__(256, 2) void tc_gemm(
    const __nv_bfloat16* __restrict__ A, const __nv_bfloat16* __restrict__ W,
    int K3, int N, int nchunks,
    float* __restrict__ Cf, __nv_bfloat16* __restrict__ Cs, int KsegOut,
    const float* __restrict__ bias, const float* __restrict__ ls,
    const float* __restrict__ res)
{
    extern __shared__ __nv_bfloat16 dsm[];
    __nv_bfloat16* Asm = dsm;
    __nv_bfloat16* Bsm = dsm + NSTAGE * STAGE_H;

    int tid = threadIdx.x, lane = tid & 31, wid = tid >> 5;
    __builtin_assume(tid < 256);
    int wm = wid & 1, wn = wid >> 1;
    int m0 = blockIdx.y * 128, n0 = blockIdx.x * 128;

    float acc[4][4][4] = {};

    auto load_chunk = [&](int c, int buf) {
        int k0 = c * 32;
        #pragma unroll
        for (int rep = 0; rep < 2; rep++) {
            int u = tid + rep * 256;
            int row = u >> 2, q = u & 3;
            uint32_t da = cvta_s(&Asm[buf * STAGE_H + row * GPITCH + q * 8]);
            uint32_t db = cvta_s(&Bsm[buf * STAGE_H + row * GPITCH + q * 8]);
            CP_ASYNC16(da, A + (size_t)(m0 + row) * K3 + k0 + q * 8);
            CP_ASYNC16(db, W + (size_t)(n0 + row) * K3 + k0 + q * 8);
        }
        CP_COMMIT();
    };

    load_chunk(0, 0);
    load_chunk(1, 1);

    int cbuf = 0, lbuf = 2;
    for (int c = 0; c < nchunks; c++) {
        CP_WAIT1();
        __syncthreads();
        if (c + 2 < nchunks) load_chunk(c + 2, lbuf);
        else                 CP_COMMIT();

        const __nv_bfloat16* Ab = Asm + cbuf * STAGE_H;
        const __nv_bfloat16* Bb = Bsm + cbuf * STAGE_H;
        #pragma unroll
        for (int kk = 0; kk < 32; kk += 16) {
            int kc = kk + (lane & 3) * 2;
            uint32_t af[4][4], bf[4][2];
            #pragma unroll
            for (int mi = 0; mi < 4; mi++) {
                int r = wm * 64 + mi * 16 + (lane >> 2);
                af[mi][0] = *(const uint32_t*)&Ab[r * GPITCH + kc];
                af[mi][1] = *(const uint32_t*)&Ab[(r + 8) * GPITCH + kc];
                af[mi][2] = *(const uint32_t*)&Ab[r * GPITCH + kc + 8];
                af[mi][3] = *(const uint32_t*)&Ab[(r + 8) * GPITCH + kc + 8];
            }
            #pragma unroll
            for (int ni = 0; ni < 4; ni++) {
                int n = wn * 32 + ni * 8 + (lane >> 2);
                bf[ni][0] = *(const uint32_t*)&Bb[n * GPITCH + kc];
                bf[ni][1] = *(const uint32_t*)&Bb[n * GPITCH + kc + 8];
            }
            #pragma unroll
            for (int mi = 0; mi < 4; mi++)
                #pragma unroll
                for (int ni = 0; ni < 4; ni++)
                    mma16816(acc[mi][ni], af[mi], bf[ni]);
        }
        cbuf = (cbuf == 2) ? 0 : cbuf + 1;
        lbuf = (lbuf == 2) ? 0 : lbuf + 1;
    }

    #pragma unroll
    for (int mi = 0; mi < 4; mi++) {
        #pragma unroll
        for (int ni = 0; ni < 4; ni++) {
            int col = n0 + wn * 32 + ni * 8 + (lane & 3) * 2;
            #pragma unroll
            for (int hh = 0; hh < 2; hh++) {
                int m = m0 + wm * 64 + mi * 16 + (lane >> 2) + hh * 8;
                float v0 = acc[mi][ni][hh * 2 + 0];
                float v1 = acc[mi][ni][hh * 2 + 1];
                if (EPI == 1) {
                    #pragma unroll
                    for (int e = 0; e < 2; e++) {
                        float v = (e ? v1 : v0) + bias[col + e];
                        v = 0.5f * v * (1.0f + erff(v * 0.70710678118654752f));
                        Cs[(size_t)m * KsegOut + col + e] = __float2bfloat16(v);
                    }
                } else if (EPI == 2) {
                    size_t i0 = (size_t)m * N + col;
                    Cf[i0]     = (v0 + bias[col])     * ls[col]     + res[i0];
                    Cf[i0 + 1] = (v1 + bias[col + 1]) * ls[col + 1] + res[i0 + 1];
                } else {   // EPI == 3: plain bf16
                    Cs[(size_t)m * N + col]     = __float2bfloat16(v0);
                    Cs[(size_t)m * N + col + 1] = __float2bfloat16(v1);
                }
            }
        }
    }
}

// ---------------------------------------------------------------------------
// dots via HMMA: per z=(b,h) tile 128x128, K=64. q,k bf16 from fused qkv.
// grid (2, 2, 192). dots written bf16 (scaled), paired stores.
// ---------------------------------------------------------------------------
#define DP 72    // halves pitch

__global__ __launch_bounds__(256) void dots_mma(
    const __nv_bfloat16* __restrict__ qkv, const float* __restrict__ scale,
    __nv_bfloat16* __restrict__ dots)
{
    __shared__ __nv_bfloat16 Qs[128 * DP];
    __shared__ __nv_bfloat16 Ks[128 * DP];

    int z = blockIdx.z;
    int b = z / HH, h = z % HH;
    int i0 = blockIdx.y * 128, j0 = blockIdx.x * 128;

    int tid = threadIdx.x, lane = tid & 31, wid = tid >> 5;
    __builtin_assume(tid < 256);
    int wm = wid & 1, wn = wid >> 1;

    #pragma unroll
    for (int it = 0; it < 4; it++) {
        int u = tid + it * 256;
        int r = u >> 3, q = u & 7;
        *(uint4*)&Qs[r * DP + q * 8] =
            *(const uint4*)&qkv[(size_t)(b * NN + i0 + r) * K3Q + h * DHD + q * 8];
        *(uint4*)&Ks[r * DP + q * 8] =
            *(const uint4*)&qkv[(size_t)(b * NN + j0 + r) * K3Q + 384 + h * DHD + q * 8];
    }
    __syncthreads();

    float acc[4][4][4] = {};
    #pragma unroll
    for (int kk = 0; kk < 64; kk += 16) {
        int kc = kk + (lane & 3) * 2;
        uint32_t af[4][4], bf[4][2];
        #pragma unroll
        for (int mi = 0; mi < 4; mi++) {
            int r = wm * 64 + mi * 16 + (lane >> 2);
            af[mi][0] = *(const uint32_t*)&Qs[r * DP + kc];
            af[mi][1] = *(const uint32_t*)&Qs[(r + 8) * DP + kc];
            af[mi][2] = *(const uint32_t*)&Qs[r * DP + kc + 8];
            af[mi][3] = *(const uint32_t*)&Qs[(r + 8) * DP + kc + 8];
        }
        #pragma unroll
        for (int ni = 0; ni < 4; ni++) {
            int n = wn * 32 + ni * 8 + (lane >> 2);
            bf[ni][0] = *(const uint32_t*)&Ks[n * DP + kc];
            bf[ni][1] = *(const uint32_t*)&Ks[n * DP + kc + 8];
        }
        #pragma unroll
        for (int mi = 0; mi < 4; mi++)
            #pragma unroll
            for (int ni = 0; ni < 4; ni++)
                mma16816(acc[mi][ni], af[mi], bf[ni]);
    }

    float sc = scale[h];
    __nv_bfloat16* C = dots + (size_t)z * NN * NN;
    #pragma unroll
    for (int mi = 0; mi < 4; mi++)
        #pragma unroll
        for (int ni = 0; ni < 4; ni++) {
            int col = j0 + wn * 32 + ni * 8 + (lane & 3) * 2;
            #pragma unroll
            for (int hh = 0; hh < 2; hh++) {
                int m = i0 + wm * 64 + mi * 16 + (lane >> 2) + hh * 8;
                __nv_bfloat162 p;
                p.x = __float2bfloat16(acc[mi][ni][hh * 2 + 0] * sc);
                p.y = __float2bfloat16(acc[mi][ni][hh * 2 + 1] * sc);
                *(__nv_bfloat162*)&C[(size_t)m * NN + col] = p;
            }
        }
}

// ---------------------------------------------------------------------------
// Fused pre-mix -> mask -> softmax -> post-mix; bf16 in, bf16 out
// ---------------------------------------------------------------------------
__global__ __launch_bounds__(256) void softmax_mix_kernel(
    const __nv_bfloat16* __restrict__ dots, const float* __restrict__ mp,
    const float* __restrict__ mq, __nv_bfloat16* __restrict__ attn)
{
    int b = blockIdx.x >> 8;
    int i = blockIdx.x & 255;
    int j = threadIdx.x;
    int lane = j & 31, wrp = j >> 5;

    __shared__ float smp[36], smq[36];
    __shared__ float red[8][6];
    if (j < 36) { smp[j] = mp[j]; smq[j] = mq[j]; }

    float raw[HH];
    #pragma unroll
    for (int h = 0; h < HH; h++)
        raw[h] = __bfloat162float(dots[(((size_t)(b * HH + h)) * NN + i) * NN + j]);
    __syncthreads();

    float pm[HH];
    #pragma unroll
    for (int g = 0; g < HH; g++) {
        float s = 0.0f;
        #pragma unroll
        for (int h = 0; h < HH; h++) s = fmaf(raw[h], smp[h * HH + g], s);
        pm[g] = s;
    }
    if (j == i) {
        #pragma unroll
        for (int g = 0; g < HH; g++) pm[g] = -INFINITY;
    }

    float mx[HH];
    #pragma unroll
    for (int g = 0; g < HH; g++) mx[g] = pm[g];
    #pragma unroll
    for (int o = 16; o; o >>= 1)
        #pragma unroll
        for (int g = 0; g < HH; g++)
            mx[g] = fmaxf(mx[g], __shfl_xor_sync(0xffffffffu, mx[g], o));
    if (lane == 0)
        #pragma unroll
        for (int g = 0; g < HH; g++) red[wrp][g] = mx[g];
    __syncthreads();
    #pragma unroll
    for (int g = 0; g < HH; g++) {
        float m = red[0][g];
        #pragma unroll
        for (int w = 1; w < 8; w++) m = fmaxf(m, red[w][g]);
        mx[g] = m;
    }
    __syncthreads();

    float ex[HH], sm[HH];
    #pragma unroll
    for (int g = 0; g < HH; g++) { ex[g] = expf(pm[g] - mx[g]); sm[g] = ex[g]; }
    #pragma unroll
    for (int o = 16; o; o >>= 1)
        #pragma unroll
        for (int g = 0; g < HH; g++)
            sm[g] += __shfl_xor_sync(0xffffffffu, sm[g], o);
    if (lane == 0)
        #pragma unroll
        for (int g = 0; g < HH; g++) red[wrp][g] = sm[g];
    __syncthreads();
    float a[HH];
    #pragma unroll
    for (int g = 0; g < HH; g++) {
        float s = red[0][g];
        #pragma unroll
        for (int w = 1; w < 8; w++) s += red[w][g];
        a[g] = ex[g] / s;
    }

    #pragma unroll
    for (int g = 0; g < HH; g++) {
        float s = 0.0f;
        #pragma unroll
        for (int h = 0; h < HH; h++) s = fmaf(a[h], smq[h * HH + g], s);
        attn[(((size_t)(b * HH + g)) * NN + i) * NN + j] = __float2bfloat16(s);
    }
}

// ---------------------------------------------------------------------------
// attn*V via HMMA: per z=(b,h): O[256,64] = attn[z](bf16) x v[z](bf16), K=256.
// Tile 128x64, 8 warps (4M x 2N, 32x32 each). V transposed in smem.
// grid (2, 192). Writes g_op bf16.
// ---------------------------------------------------------------------------
__global__ __launch_bounds__(256) void attnv_mma(
    const __nv_bfloat16* __restrict__ attn, const __nv_bfloat16* __restrict__ qkv,
    __nv_bfloat16* __restrict__ op)
{
    __shared__ __nv_bfloat16 As[128 * DP];     // attn tile
    __shared__ __nv_bfloat16 Vs16[64][DP];     // V staging [j][d]
    __shared__ __nv_bfloat16 Vst[64 * DP];     // V^T [d][j]

    int z = blockIdx.y;
    int b = z / HH, h = z % HH;
    int i0 = blockIdx.x * 128;

    int tid = threadIdx.x, lane = tid & 31, wid = tid >> 5;
    __builtin_assume(tid < 256);
    int wm = wid & 3, wn = wid >> 2;

    const __nv_bfloat16* abase = attn + (size_t)z * NN * NN;
    const __nv_bfloat16* vbase = qkv + 768 + h * DHD;

    float acc[2][4][4] = {};

    for (int c = 0; c < 4; c++) {
        int j0 = c * 64;
        #pragma unroll
        for (int it = 0; it < 4; it++) {
            int u = tid + it * 256;
            int r = u >> 3, q = u & 7;
            *(uint4*)&As[r * DP + q * 8] =
                *(const uint4*)&abase[(size_t)(i0 + r) * NN + j0 + q * 8];
        }
        #pragma unroll
        for (int it = 0; it < 2; it++) {
            int u = tid + it * 256;
            int r = u >> 3, q = u & 7;
            *(uint4*)&Vs16[r][q * 8] =
                *(const uint4*)&vbase[(size_t)(b * NN + j0 + r) * K3Q + q * 8];
        }
        __syncthreads();
        #pragma unroll
        for (int it = 0; it < 8; it++) {
            int u = tid + it * 256;
            int d = u & 63, jp = u >> 6;
            __nv_bfloat162 p;
            p.x = Vs16[2 * jp][d];
            p.y = Vs16[2 * jp + 1][d];
            *(__nv_bfloat162*)&Vst[d * DP + jp * 2] = p;
        }
        __syncthreads();

        #pragma unroll
        for (int kk = 0; kk < 64; kk += 16) {
            int kc = kk + (lane & 3) * 2;
            uint32_t af[2][4], bf[4][2];
            #pragma unroll
            for (int mi = 0; mi < 2; mi++) {
                int r = wm * 32 + mi * 16 + (lane >> 2);
                af[mi][0] = *(const uint32_t*)&As[r * DP + kc];
                af[mi][1] = *(const uint32_t*)&As[(r + 8) * DP + kc];
                af[mi][2] = *(const uint32_t*)&As[r * DP + kc + 8];
                af[mi][3] = *(const uint32_t*)&As[(r + 8) * DP + kc + 8];
            }
            #pragma unroll
            for (int ni = 0; ni < 4; ni++) {
                int n = wn * 32 + ni * 8 + (lane >> 2);
                bf[ni][0] = *(const uint32_t*)&Vst[n * DP + kc];
                bf[ni][1] = *(const uint32_t*)&Vst[n * DP + kc + 8];
            }
            #pragma unroll
            for (int mi = 0; mi < 2; mi++)
                #pragma unroll
                for (int ni = 0; ni < 4; ni++)
                    mma16816(acc[mi][ni], af[mi], bf[ni]);
        }
        __syncthreads();
    }

    #pragma unroll
    for (int mi = 0; mi < 2; mi++)
        #pragma unroll
        for (int ni = 0; ni < 4; ni++) {
            int d0 = wn * 32 + ni * 8 + (lane & 3) * 2;
            #pragma unroll
            for (int hh = 0; hh < 2; hh++) {
                int i = i0 + wm * 32 + mi * 16 + (lane >> 2) + hh * 8;
                size_t row = (size_t)b * NN + i;
                op[row * DIMD + h * DHD + d0]     =
                    __float2bfloat16(acc[mi][ni][hh * 2 + 0]);
                op[row * DIMD + h * DHD + d0 + 1] =
                    __float2bfloat16(acc[mi][ni][hh * 2 + 1]);
            }
        }
}

// ---------------------------------------------------------------------------
// Launch
// ---------------------------------------------------------------------------
extern "C" void kernel_launch(void* const* d_in, const int* in_sizes, int n_in,
                              void* d_out, int out_size)
{
    const float* x    = (const float*)d_in[0];
    const float* ln1g = (const float*)d_in[1];
    const float* ln1b = (const float*)d_in[2];
    const float* wq   = (const float*)d_in[3];
    const float* wkv  = (const float*)d_in[4];
    const float* scl  = (const float*)d_in[5];
    const float* mp   = (const float*)d_in[6];
    const float* mq   = (const float*)d_in[7];
    const float* wo   = (const float*)d_in[8];
    const float* bo   = (const float*)d_in[9];
    const float* ls1  = (const float*)d_in[10];
    const float* ln2g = (const float*)d_in[11];
    const float* ln2b = (const float*)d_in[12];
    const float* w1   = (const float*)d_in[13];
    const float* b1   = (const float*)d_in[14];
    const float* w2   = (const float*)d_in[15];
    const float* b2   = (const float*)d_in[16];
    const float* ls2  = (const float*)d_in[17];

    cudaFuncSetAttribute(tc_gemm<1>, cudaFuncAttributeMaxDynamicSharedMemorySize, GEMM_DSMEM);
    cudaFuncSetAttribute(tc_gemm<2>, cudaFuncAttributeMaxDynamicSharedMemorySize, GEMM_DSMEM);
    cudaFuncSetAttribute(tc_gemm<3>, cudaFuncAttributeMaxDynamicSharedMemorySize, GEMM_DSMEM);

    float* gx;
    __nv_bfloat16 *gdots, *gqkv, *gattn, *gyp, *gop, *ghp, *gwqkvp, *gwop, *gw1p, *gw2p;
    cudaGetSymbolAddress((void**)&gx,     g_x);
    cudaGetSymbolAddress((void**)&gqkv,   g_qkv);
    cudaGetSymbolAddress((void**)&gdots,  g_dots);
    cudaGetSymbolAddress((void**)&gattn,  g_attn);
    cudaGetSymbolAddress((void**)&gyp,    g_yp);
    cudaGetSymbolAddress((void**)&gop,    g_op);
    cudaGetSymbolAddress((void**)&ghp,    g_hp);
    cudaGetSymbolAddress((void**)&gwqkvp, g_wqkvp);
    cudaGetSymbolAddress((void**)&gwop,   g_wop);
    cudaGetSymbolAddress((void**)&gw1p,   g_w1p);
    cudaGetSymbolAddress((void**)&gw2p,   g_w2p);

    cudaMemcpyAsync(gx, x, (size_t)BN_ROWS * DIMD * sizeof(float),
                    cudaMemcpyDeviceToDevice, 0);

    // Batched weight transpose -> bf16 (grid.z = DEPTH)
    wconv_kernel<<<dim3(384/32, 384/32, DEPTH), 256>>>(
        wq,  gwqkvp, 384, 384,  0,   (size_t)DIMD*INNERD,   (size_t)1152*DIMD);
    wconv_kernel<<<dim3(768/32, 384/32, DEPTH), 256>>>(
        wkv, gwqkvp, 384, 768,  384, (size_t)DIMD*2*INNERD, (size_t)1152*DIMD);
    wconv_kernel<<<dim3(384/32, 384/32, DEPTH), 256>>>(
        wo,  gwop,   384, 384,  0,   (size_t)INNERD*DIMD,   (size_t)384*DIMD);
    wconv_kernel<<<dim3(1536/32, 384/32, DEPTH), 256>>>(
        w1,  gw1p,   384, 1536, 0,   (size_t)DIMD*MLPD,     (size_t)1536*DIMD);
    wconv_kernel<<<dim3(384/32, 1536/32, DEPTH), 256>>>(
        w2,  gw2p,   1536, 384, 0,   (size_t)MLPD*DIMD,     (size_t)384*MLPD);

    for (int L = 0; L < DEPTH; L++) {
        const __nv_bfloat16* L_wqkvp = gwqkvp + (size_t)L*1152*DIMD;
        const __nv_bfloat16* L_wop   = gwop   + (size_t)L*384*DIMD;
        const __nv_bfloat16* L_w1p   = gw1p   + (size_t)L*1536*DIMD;
        const __nv_bfloat16* L_w2p   = gw2p   + (size_t)L*384*MLPD;

        // Attention
        ln_bf16_kernel<<<BN_ROWS, 128>>>(gx, ln1g + L*DIMD, ln1b + L*DIMD, gyp);
        tc_gemm<3><<<dim3(1152/128, BN_ROWS/128), 256, GEMM_DSMEM>>>(
            gyp, L_wqkvp, DIMD, 1152, DIMD/32, nullptr, gqkv, 0,
            nullptr, nullptr, nullptr);
        dots_mma<<<dim3(2, 2, BB*HH), 256>>>(gqkv, scl + L*HH, gdots);
        softmax_mix_kernel<<<BB*NN, 256>>>(gdots, mp + L*HH*HH, mq + L*HH*HH, gattn);
        attnv_mma<<<dim3(2, BB*HH), 256>>>(gattn, gqkv, gop);
        tc_gemm<2><<<dim3(384/128, BN_ROWS/128), 256, GEMM_DSMEM>>>(
            gop, L_wop, DIMD, 384, DIMD/32, gx, nullptr, 0,
            bo + L*DIMD, ls1 + L*DIMD, gx);

        // FFN
        ln_bf16_kernel<<<BN_ROWS, 128>>>(gx, ln2g + L*DIMD, ln2b + L*DIMD, gyp);
        tc_gemm<1><<<dim3(1536/128, BN_ROWS/128), 256, GEMM_DSMEM>>>(
            gyp, L_w1p, DIMD, 1536, DIMD/32, nullptr, ghp, MLPD,
            b1 + L*MLPD, nullptr, nullptr);
        tc_gemm<2><<<dim3(384/128, BN_ROWS/128), 256, GEMM_DSMEM>>>(
            ghp, L_w2p, MLPD, 384, MLPD/32, gx, nullptr, 0,
            b2 + L*DIMD, ls2 + L*DIMD, gx);
    }

    cudaMemcpyAsync(d_out, gx, (size_t)BN_ROWS * DIMD * sizeof(float),
                    cudaMemcpyDeviceToDevice, 0);
}